// round 2
// baseline (speedup 1.0000x reference)
#include <cuda_runtime.h>

#define N_NODES  100000
#define N_EDGES  1600000
#define N_GRAPHS 512

// ---------------- device scratch (no allocations allowed) ----------------
__device__ float g_h0[N_NODES * 32];     // after pre-MLP
__device__ float g_h1[N_NODES * 64];     // after conv1
__device__ float g_agg[N_NODES * 64];    // reused: conv1 (stride 32), conv2 (stride 64)
__device__ int   g_cnt[N_NODES];         // in-degree
__device__ float g_gsum[N_GRAPHS * 64];  // graph pooling sums
__device__ int   g_gcnt[N_GRAPHS];       // nodes per graph

// vectorized L2 reduction (sm_90+): 4 floats per atomic op
__device__ __forceinline__ void red_add_v4(float* addr, float4 v) {
    asm volatile("red.global.add.v4.f32 [%0], {%1,%2,%3,%4};"
                 :: "l"(addr), "f"(v.x), "f"(v.y), "f"(v.z), "f"(v.w)
                 : "memory");
}

// ---------------- kernels ----------------

// zero agg (full 64-wide region), cnt, gsum, gcnt
__global__ void k_zero_all() {
    int i = blockIdx.x * blockDim.x + threadIdx.x;
    int n4 = N_NODES * 16;                 // N_NODES*64/4 float4s
    if (i < n4) ((float4*)g_agg)[i] = make_float4(0.f, 0.f, 0.f, 0.f);
    if (i < N_NODES) g_cnt[i] = 0;
    if (i < N_GRAPHS * 64) g_gsum[i] = 0.f;
    if (i < N_GRAPHS) g_gcnt[i] = 0;
}

__global__ void k_zero_agg() {
    int i = blockIdx.x * blockDim.x + threadIdx.x;
    int n4 = N_NODES * 16;
    if (i < n4) ((float4*)g_agg)[i] = make_float4(0.f, 0.f, 0.f, 0.f);
}

__global__ void k_hist(const int* __restrict__ dst) {
    int e = blockIdx.x * blockDim.x + threadIdx.x;
    if (e < N_EDGES) atomicAdd(&g_cnt[dst[e]], 1);
}

// pre: h0 = relu(x @ pre_w + pre_b), thread-per-node
__global__ void k_pre(const float* __restrict__ x,
                      const float* __restrict__ w,
                      const float* __restrict__ b) {
    __shared__ float sw[5 * 32];
    __shared__ float sb[32];
    int t = threadIdx.x;
    if (t < 160) sw[t] = w[t];
    if (t < 32)  sb[t] = b[t];
    __syncthreads();
    int n = blockIdx.x * blockDim.x + t;
    if (n >= N_NODES) return;
    float xi[5];
#pragma unroll
    for (int i = 0; i < 5; i++) xi[i] = x[n * 5 + i];
    float4* outp = (float4*)&g_h0[n * 32];
#pragma unroll
    for (int j4 = 0; j4 < 8; j4++) {
        float4 v;
        float* vv = (float*)&v;
#pragma unroll
        for (int q = 0; q < 4; q++) {
            int j = j4 * 4 + q;
            float s = sb[j];
#pragma unroll
            for (int i = 0; i < 5; i++) s += xi[i] * sw[i * 32 + j];
            vv[q] = fmaxf(s, 0.f);
        }
        outp[j4] = v;
    }
}

// conv1 scatter: 8 threads per edge, each moves 4 floats (32 feats total)
__global__ void k_scatter1(const int* __restrict__ src, const int* __restrict__ dst) {
    long tid = (long)blockIdx.x * blockDim.x + threadIdx.x;
    int e = (int)(tid >> 3);
    if (e >= N_EDGES) return;
    int l = (int)(tid & 7);
    int s = src[e], d = dst[e];
    float4 v = *(const float4*)&g_h0[s * 32 + l * 4];
    red_add_v4(&g_agg[d * 32 + l * 4], v);
}

// conv1 combine: out = agg/cnt @ wl + bl + h0 @ wr ; L2 normalize ; relu
// warp per node, 8 warps / block, weights in SMEM
__global__ void k_combine1(const float* __restrict__ wl,
                           const float* __restrict__ bl,
                           const float* __restrict__ wr) {
    __shared__ float swl[32 * 64], swr[32 * 64], sb[64];
    int t = threadIdx.x;
    for (int i = t; i < 2048; i += 256) { swl[i] = wl[i]; swr[i] = wr[i]; }
    if (t < 64) sb[t] = bl[t];
    __syncthreads();
    int warp = t >> 5, lane = t & 31;
    int n = blockIdx.x * 8 + warp;
    if (n >= N_NODES) return;
    int c = g_cnt[n];
    float inv = c > 0 ? 1.0f / (float)c : 0.0f;
    float a = g_agg[n * 32 + lane] * inv;
    float h = g_h0[n * 32 + lane];
    float acc0 = sb[lane], acc1 = sb[lane + 32];
#pragma unroll
    for (int k = 0; k < 32; k++) {
        float ak = __shfl_sync(0xffffffffu, a, k);
        float hk = __shfl_sync(0xffffffffu, h, k);
        acc0 += ak * swl[k * 64 + lane]      + hk * swr[k * 64 + lane];
        acc1 += ak * swl[k * 64 + lane + 32] + hk * swr[k * 64 + lane + 32];
    }
    float ss = acc0 * acc0 + acc1 * acc1;
#pragma unroll
    for (int o = 16; o; o >>= 1) ss += __shfl_xor_sync(0xffffffffu, ss, o);
    float in2 = 1.0f / fmaxf(sqrtf(ss), 1e-12f);
    g_h1[n * 64 + lane]      = fmaxf(acc0 * in2, 0.f);
    g_h1[n * 64 + lane + 32] = fmaxf(acc1 * in2, 0.f);
}

// conv2 scatter: 16 threads per edge (64 feats)
__global__ void k_scatter2(const int* __restrict__ src, const int* __restrict__ dst) {
    long tid = (long)blockIdx.x * blockDim.x + threadIdx.x;
    int e = (int)(tid >> 4);
    if (e >= N_EDGES) return;
    int l = (int)(tid & 15);
    int s = src[e], d = dst[e];
    float4 v = *(const float4*)&g_h1[s * 64 + l * 4];
    red_add_v4(&g_agg[d * 64 + l * 4], v);
}

// conv2 combine + graph mean-pool accumulation
__global__ void k_combine2(const float* __restrict__ wl,
                           const float* __restrict__ bl,
                           const float* __restrict__ wr,
                           const int* __restrict__ batch) {
    __shared__ float swl[64 * 64], swr[64 * 64], sb[64];
    int t = threadIdx.x;
    for (int i = t; i < 4096; i += 256) { swl[i] = wl[i]; swr[i] = wr[i]; }
    if (t < 64) sb[t] = bl[t];
    __syncthreads();
    int warp = t >> 5, lane = t & 31;
    int n = blockIdx.x * 8 + warp;
    if (n >= N_NODES) return;
    int c = g_cnt[n];
    float inv = c > 0 ? 1.0f / (float)c : 0.0f;
    float a0 = g_agg[n * 64 + lane] * inv;
    float a1 = g_agg[n * 64 + lane + 32] * inv;
    float h0v = g_h1[n * 64 + lane];
    float h1v = g_h1[n * 64 + lane + 32];
    float acc0 = sb[lane], acc1 = sb[lane + 32];
#pragma unroll
    for (int k = 0; k < 32; k++) {
        float ak = __shfl_sync(0xffffffffu, a0, k);
        float hk = __shfl_sync(0xffffffffu, h0v, k);
        acc0 += ak * swl[k * 64 + lane]      + hk * swr[k * 64 + lane];
        acc1 += ak * swl[k * 64 + lane + 32] + hk * swr[k * 64 + lane + 32];
    }
#pragma unroll
    for (int k = 0; k < 32; k++) {
        float ak = __shfl_sync(0xffffffffu, a1, k);
        float hk = __shfl_sync(0xffffffffu, h1v, k);
        int kk = k + 32;
        acc0 += ak * swl[kk * 64 + lane]      + hk * swr[kk * 64 + lane];
        acc1 += ak * swl[kk * 64 + lane + 32] + hk * swr[kk * 64 + lane + 32];
    }
    float ss = acc0 * acc0 + acc1 * acc1;
#pragma unroll
    for (int o = 16; o; o >>= 1) ss += __shfl_xor_sync(0xffffffffu, ss, o);
    float in2 = 1.0f / fmaxf(sqrtf(ss), 1e-12f);
    float o0 = fmaxf(acc0 * in2, 0.f);
    float o1 = fmaxf(acc1 * in2, 0.f);
    int b = batch[n];
    atomicAdd(&g_gsum[b * 64 + lane], o0);
    atomicAdd(&g_gsum[b * 64 + lane + 32], o1);
    if (lane == 0) atomicAdd(&g_gcnt[b], 1);
}

// per-graph head: mean -> relu(64x64) -> relu(64x16) -> 16x1
__global__ void k_head(const float* __restrict__ p1w, const float* __restrict__ p1b,
                       const float* __restrict__ p2w, const float* __restrict__ p2b,
                       const float* __restrict__ ow,  const float* __restrict__ ob,
                       float* __restrict__ out) {
    __shared__ float sg[64], t1[64], t2[16];
    int g = blockIdx.x, t = threadIdx.x;
    float c = (float)g_gcnt[g];
    float inv = 1.0f / fmaxf(c, 1.0f);
    sg[t] = g_gsum[g * 64 + t] * inv;
    __syncthreads();
    float s = p1b[t];
#pragma unroll 8
    for (int k = 0; k < 64; k++) s += sg[k] * p1w[k * 64 + t];
    t1[t] = fmaxf(s, 0.f);
    __syncthreads();
    if (t < 16) {
        float s2 = p2b[t];
#pragma unroll 8
        for (int k = 0; k < 64; k++) s2 += t1[k] * p2w[k * 16 + t];
        t2[t] = fmaxf(s2, 0.f);
    }
    __syncthreads();
    if (t == 0) {
        float o = ob[0];
#pragma unroll
        for (int k = 0; k < 16; k++) o += t2[k] * ow[k];
        out[g] = o;
    }
}

// ---------------- launch ----------------
extern "C" void kernel_launch(void* const* d_in, const int* in_sizes, int n_in,
                              void* d_out, int out_size) {
    const float* x     = (const float*)d_in[0];
    const int*   ei    = (const int*)d_in[1];
    const int*   batch = (const int*)d_in[2];
    // num_graphs may or may not be materialized as a tensor input
    int base = (n_in >= 18 && in_sizes[3] == 1) ? 4 : 3;
    const float* pre_w = (const float*)d_in[base + 0];
    const float* pre_b = (const float*)d_in[base + 1];
    const float* c1_wl = (const float*)d_in[base + 2];
    const float* c1_bl = (const float*)d_in[base + 3];
    const float* c1_wr = (const float*)d_in[base + 4];
    const float* c2_wl = (const float*)d_in[base + 5];
    const float* c2_bl = (const float*)d_in[base + 6];
    const float* c2_wr = (const float*)d_in[base + 7];
    const float* p1_w  = (const float*)d_in[base + 8];
    const float* p1_b  = (const float*)d_in[base + 9];
    const float* p2_w  = (const float*)d_in[base + 10];
    const float* p2_b  = (const float*)d_in[base + 11];
    const float* o_w   = (const float*)d_in[base + 12];
    const float* o_b   = (const float*)d_in[base + 13];

    const int* src = ei;             // edge_index[0]
    const int* dst = ei + N_EDGES;   // edge_index[1]
    float* out = (float*)d_out;

    const int T = 256;
    int zb = (N_NODES * 16 + T - 1) / T;          // 1.6M threads
    k_zero_all<<<zb, T>>>();
    k_pre<<<(N_NODES + T - 1) / T, T>>>(x, pre_w, pre_b);
    k_hist<<<(N_EDGES + T - 1) / T, T>>>(dst);

    long s1 = (long)N_EDGES * 8;
    k_scatter1<<<(int)((s1 + T - 1) / T), T>>>(src, dst);
    k_combine1<<<(N_NODES + 7) / 8, T>>>(c1_wl, c1_bl, c1_wr);

    k_zero_agg<<<zb, T>>>();
    long s2 = (long)N_EDGES * 16;
    k_scatter2<<<(int)((s2 + T - 1) / T), T>>>(src, dst);
    k_combine2<<<(N_NODES + 7) / 8, T>>>(c2_wl, c2_bl, c2_wr, batch);

    k_head<<<N_GRAPHS, 64>>>(p1_w, p1_b, p2_w, p2_b, o_w, o_b, out);
    (void)out_size;
}

// round 3
// speedup vs baseline: 1.1556x; 1.1556x over previous
#include <cuda_runtime.h>

#define N_NODES  100000
#define N_EDGES  1600000
#define N_GRAPHS 512
#define NB_SCAN  ((N_NODES + 1023) / 1024)   // 98

// ---------------- device scratch (no allocations allowed) ----------------
__device__ float g_h0[N_NODES * 32];
__device__ float g_h1[N_NODES * 64];
__device__ float g_h2[N_NODES * 64];
__device__ int   g_cnt[N_NODES];        // in-degree
__device__ int   g_rs[N_NODES];         // CSR row start (exclusive scan of cnt)
__device__ int   g_cur[N_NODES];        // fill cursors
__device__ int   g_adj[N_EDGES];        // CSR adjacency (src per dst)
__device__ int   g_bsum[NB_SCAN + 8];   // scan block sums
__device__ int   g_lo[N_GRAPHS + 1];    // graph node-range starts

// ---------------- CSR build ----------------
__global__ void k_zero_cnt() {
    int i = blockIdx.x * blockDim.x + threadIdx.x;
    if (i < N_NODES) g_cnt[i] = 0;
}

__global__ void k_hist(const int* __restrict__ dst) {
    int e = blockIdx.x * blockDim.x + threadIdx.x;
    if (e < N_EDGES) atomicAdd(&g_cnt[dst[e]], 1);
}

// scan stage 1: per-1024-chunk exclusive scan, block totals to g_bsum
__global__ void k_scan1() {
    __shared__ int wsum[8];
    int b = blockIdx.x, t = threadIdx.x;
    int lane = t & 31, w = t >> 5;
    int base = b * 1024 + t * 4;
    int v[4];
#pragma unroll
    for (int q = 0; q < 4; q++) v[q] = (base + q < N_NODES) ? g_cnt[base + q] : 0;
    int tot = v[0] + v[1] + v[2] + v[3];
    int sc = tot;
#pragma unroll
    for (int o = 1; o < 32; o <<= 1) {
        int x = __shfl_up_sync(0xffffffffu, sc, o);
        if (lane >= o) sc += x;
    }
    if (lane == 31) wsum[w] = sc;
    __syncthreads();
    if (t == 0) {
        int r = 0;
#pragma unroll
        for (int i = 0; i < 8; i++) { int x = wsum[i]; wsum[i] = r; r += x; }
        g_bsum[b] = r;
    }
    __syncthreads();
    int run = wsum[w] + (sc - tot);
#pragma unroll
    for (int q = 0; q < 4; q++) {
        if (base + q < N_NODES) g_rs[base + q] = run;
        run += v[q];
    }
}

// scan stage 2: exclusive scan of the 98 block sums (single block)
__global__ void k_scan2() {
    __shared__ int sb[NB_SCAN];
    int t = threadIdx.x;
    if (t < NB_SCAN) sb[t] = g_bsum[t];
    __syncthreads();
    if (t == 0) {
        int r = 0;
        for (int i = 0; i < NB_SCAN; i++) { int x = sb[i]; sb[i] = r; r += x; }
    }
    __syncthreads();
    if (t < NB_SCAN) g_bsum[t] = sb[t];
}

// scan stage 3: add block offsets, init cursors
__global__ void k_scan3() {
    int i = blockIdx.x * blockDim.x + threadIdx.x;
    if (i >= N_NODES) return;
    int v = g_rs[i] + g_bsum[i >> 10];
    g_rs[i] = v;
    g_cur[i] = v;
}

__global__ void k_fill(const int* __restrict__ src, const int* __restrict__ dst) {
    int e = blockIdx.x * blockDim.x + threadIdx.x;
    if (e >= N_EDGES) return;
    int d = dst[e];
    int pos = atomicAdd(&g_cur[d], 1);
    g_adj[pos] = src[e];
}

// graph boundaries: batch is sorted; binary search per graph id
__global__ void k_bounds(const int* __restrict__ batch) {
    int g = blockIdx.x * blockDim.x + threadIdx.x;
    if (g > N_GRAPHS) return;
    int lo = 0, hi = N_NODES;
    while (lo < hi) {
        int m = (lo + hi) >> 1;
        if (batch[m] < g) lo = m + 1; else hi = m;
    }
    g_lo[g] = lo;
}

// ---------------- pre: h0 = relu(x @ pre_w + pre_b) ----------------
__global__ void k_pre(const float* __restrict__ x,
                      const float* __restrict__ w,
                      const float* __restrict__ b) {
    __shared__ float sw[5 * 32];
    __shared__ float sb[32];
    int t = threadIdx.x;
    if (t < 160) sw[t] = w[t];
    if (t < 32)  sb[t] = b[t];
    __syncthreads();
    int n = blockIdx.x * blockDim.x + t;
    if (n >= N_NODES) return;
    float xi[5];
#pragma unroll
    for (int i = 0; i < 5; i++) xi[i] = x[n * 5 + i];
    float4* outp = (float4*)&g_h0[n * 32];
#pragma unroll
    for (int j4 = 0; j4 < 8; j4++) {
        float4 v;
        float* vv = (float*)&v;
#pragma unroll
        for (int q = 0; q < 4; q++) {
            int j = j4 * 4 + q;
            float s = sb[j];
#pragma unroll
            for (int i = 0; i < 5; i++) s += xi[i] * sw[i * 32 + j];
            vv[q] = fmaxf(s, 0.f);
        }
        outp[j4] = v;
    }
}

// ---------------- conv1 fused: CSR gather + mean + GEMM + L2norm + relu ----
__global__ void k_conv1(const float* __restrict__ wl,
                        const float* __restrict__ bl,
                        const float* __restrict__ wr) {
    __shared__ float swl[32 * 64], swr[32 * 64], sb[64];
    int t = threadIdx.x;
    for (int i = t; i < 2048; i += 256) { swl[i] = wl[i]; swr[i] = wr[i]; }
    if (t < 64) sb[t] = bl[t];
    __syncthreads();
    int lane = t & 31, warp = t >> 5;
    int wg = blockIdx.x * 8 + warp;
    int stride = gridDim.x * 8;
    for (int n = wg; n < N_NODES; n += stride) {
        int rs = g_rs[n], d = g_cnt[n];
        float acc0 = 0.f, acc1 = 0.f;
        for (int j = 0; j < d; j += 32) {
            int chunk = min(32, d - j);
            int idx = (lane < chunk) ? g_adj[rs + j + lane] : 0;
            int q = 0;
            for (; q + 1 < chunk; q += 2) {
                int n0 = __shfl_sync(0xffffffffu, idx, q);
                int n1 = __shfl_sync(0xffffffffu, idx, q + 1);
                acc0 += g_h0[n0 * 32 + lane];
                acc1 += g_h0[n1 * 32 + lane];
            }
            if (q < chunk) {
                int n0 = __shfl_sync(0xffffffffu, idx, q);
                acc0 += g_h0[n0 * 32 + lane];
            }
        }
        float inv = d > 0 ? 1.0f / (float)d : 0.0f;
        float a = (acc0 + acc1) * inv;
        float h = g_h0[n * 32 + lane];
        float o0 = sb[lane], o1 = sb[lane + 32];
#pragma unroll
        for (int k = 0; k < 32; k++) {
            float ak = __shfl_sync(0xffffffffu, a, k);
            float hk = __shfl_sync(0xffffffffu, h, k);
            o0 += ak * swl[k * 64 + lane]      + hk * swr[k * 64 + lane];
            o1 += ak * swl[k * 64 + lane + 32] + hk * swr[k * 64 + lane + 32];
        }
        float ss = o0 * o0 + o1 * o1;
#pragma unroll
        for (int o = 16; o; o >>= 1) ss += __shfl_xor_sync(0xffffffffu, ss, o);
        float in2 = 1.0f / fmaxf(sqrtf(ss), 1e-12f);
        g_h1[n * 64 + lane]      = fmaxf(o0 * in2, 0.f);
        g_h1[n * 64 + lane + 32] = fmaxf(o1 * in2, 0.f);
    }
}

// ---------------- conv2 fused ----------------
__global__ void k_conv2(const float* __restrict__ wl,
                        const float* __restrict__ bl,
                        const float* __restrict__ wr) {
    __shared__ float swl[64 * 64], swr[64 * 64], sb[64];
    int t = threadIdx.x;
    for (int i = t; i < 4096; i += 256) { swl[i] = wl[i]; swr[i] = wr[i]; }
    if (t < 64) sb[t] = bl[t];
    __syncthreads();
    int lane = t & 31, warp = t >> 5;
    int wg = blockIdx.x * 8 + warp;
    int stride = gridDim.x * 8;
    for (int n = wg; n < N_NODES; n += stride) {
        int rs = g_rs[n], d = g_cnt[n];
        float s0 = 0.f, s1 = 0.f, s2 = 0.f, s3 = 0.f;
        for (int j = 0; j < d; j += 32) {
            int chunk = min(32, d - j);
            int idx = (lane < chunk) ? g_adj[rs + j + lane] : 0;
            int q = 0;
            for (; q + 1 < chunk; q += 2) {
                int n0 = __shfl_sync(0xffffffffu, idx, q);
                int n1 = __shfl_sync(0xffffffffu, idx, q + 1);
                s0 += g_h1[n0 * 64 + lane];
                s1 += g_h1[n0 * 64 + lane + 32];
                s2 += g_h1[n1 * 64 + lane];
                s3 += g_h1[n1 * 64 + lane + 32];
            }
            if (q < chunk) {
                int n0 = __shfl_sync(0xffffffffu, idx, q);
                s0 += g_h1[n0 * 64 + lane];
                s1 += g_h1[n0 * 64 + lane + 32];
            }
        }
        float inv = d > 0 ? 1.0f / (float)d : 0.0f;
        float a0 = (s0 + s2) * inv;
        float a1 = (s1 + s3) * inv;
        float h0v = g_h1[n * 64 + lane];
        float h1v = g_h1[n * 64 + lane + 32];
        float o0 = sb[lane], o1 = sb[lane + 32];
#pragma unroll
        for (int k = 0; k < 32; k++) {
            float ak = __shfl_sync(0xffffffffu, a0, k);
            float hk = __shfl_sync(0xffffffffu, h0v, k);
            o0 += ak * swl[k * 64 + lane]      + hk * swr[k * 64 + lane];
            o1 += ak * swl[k * 64 + lane + 32] + hk * swr[k * 64 + lane + 32];
        }
#pragma unroll
        for (int k = 0; k < 32; k++) {
            float ak = __shfl_sync(0xffffffffu, a1, k);
            float hk = __shfl_sync(0xffffffffu, h1v, k);
            int kk = k + 32;
            o0 += ak * swl[kk * 64 + lane]      + hk * swr[kk * 64 + lane];
            o1 += ak * swl[kk * 64 + lane + 32] + hk * swr[kk * 64 + lane + 32];
        }
        float ss = o0 * o0 + o1 * o1;
#pragma unroll
        for (int o = 16; o; o >>= 1) ss += __shfl_xor_sync(0xffffffffu, ss, o);
        float in2 = 1.0f / fmaxf(sqrtf(ss), 1e-12f);
        g_h2[n * 64 + lane]      = fmaxf(o0 * in2, 0.f);
        g_h2[n * 64 + lane + 32] = fmaxf(o1 * in2, 0.f);
    }
}

// ---------------- head: contiguous-range mean pool + MLP ----------------
__global__ void k_head(const float* __restrict__ p1w, const float* __restrict__ p1b,
                       const float* __restrict__ p2w, const float* __restrict__ p2b,
                       const float* __restrict__ ow,  const float* __restrict__ ob,
                       float* __restrict__ out) {
    __shared__ float part[4 * 64];
    __shared__ float sg[64], t1[64], t2[16];
    int g = blockIdx.x, t = threadIdx.x;
    int lo = g_lo[g], hi = g_lo[g + 1];
    int f = t & 63, r = t >> 6;
    float s = 0.f;
    for (int n = lo + r; n < hi; n += 4) s += g_h2[n * 64 + f];
    part[r * 64 + f] = s;
    __syncthreads();
    if (t < 64) {
        float tot = part[t] + part[64 + t] + part[128 + t] + part[192 + t];
        float cnt = (float)(hi - lo);
        sg[t] = tot / fmaxf(cnt, 1.0f);
    }
    __syncthreads();
    if (t < 64) {
        float s1 = p1b[t];
#pragma unroll 8
        for (int k = 0; k < 64; k++) s1 += sg[k] * p1w[k * 64 + t];
        t1[t] = fmaxf(s1, 0.f);
    }
    __syncthreads();
    if (t < 16) {
        float s2 = p2b[t];
#pragma unroll 8
        for (int k = 0; k < 64; k++) s2 += t1[k] * p2w[k * 16 + t];
        t2[t] = fmaxf(s2, 0.f);
    }
    __syncthreads();
    if (t == 0) {
        float o = ob[0];
#pragma unroll
        for (int k = 0; k < 16; k++) o += t2[k] * ow[k];
        out[g] = o;
    }
}

// ---------------- launch ----------------
extern "C" void kernel_launch(void* const* d_in, const int* in_sizes, int n_in,
                              void* d_out, int out_size) {
    const float* x     = (const float*)d_in[0];
    const int*   ei    = (const int*)d_in[1];
    const int*   batch = (const int*)d_in[2];
    int base = (n_in >= 18 && in_sizes[3] == 1) ? 4 : 3;
    const float* pre_w = (const float*)d_in[base + 0];
    const float* pre_b = (const float*)d_in[base + 1];
    const float* c1_wl = (const float*)d_in[base + 2];
    const float* c1_bl = (const float*)d_in[base + 3];
    const float* c1_wr = (const float*)d_in[base + 4];
    const float* c2_wl = (const float*)d_in[base + 5];
    const float* c2_bl = (const float*)d_in[base + 6];
    const float* c2_wr = (const float*)d_in[base + 7];
    const float* p1_w  = (const float*)d_in[base + 8];
    const float* p1_b  = (const float*)d_in[base + 9];
    const float* p2_w  = (const float*)d_in[base + 10];
    const float* p2_b  = (const float*)d_in[base + 11];
    const float* o_w   = (const float*)d_in[base + 12];
    const float* o_b   = (const float*)d_in[base + 13];

    const int* src = ei;
    const int* dst = ei + N_EDGES;
    float* out = (float*)d_out;

    const int T = 256;
    k_zero_cnt<<<(N_NODES + T - 1) / T, T>>>();
    k_pre<<<(N_NODES + T - 1) / T, T>>>(x, pre_w, pre_b);
    k_hist<<<(N_EDGES + T - 1) / T, T>>>(dst);
    k_scan1<<<NB_SCAN, 256>>>();
    k_scan2<<<1, 128>>>();
    k_scan3<<<(N_NODES + T - 1) / T, T>>>();
    k_fill<<<(N_EDGES + T - 1) / T, T>>>(src, dst);
    k_bounds<<<3, 256>>>(batch);

    k_conv1<<<592, 256>>>(c1_wl, c1_bl, c1_wr);
    k_conv2<<<592, 256>>>(c2_wl, c2_bl, c2_wr);

    k_head<<<N_GRAPHS, 256>>>(p1_w, p1_b, p2_w, p2_b, o_w, o_b, out);
    (void)out_size;
}

// round 4
// speedup vs baseline: 1.6931x; 1.4652x over previous
#include <cuda_runtime.h>

#define N_NODES  100000
#define N_EDGES  1600000
#define N_GRAPHS 512
#define NB_SCAN  ((N_NODES + 1023) / 1024)   // 98

// ---------------- device scratch (no allocations allowed) ----------------
__device__ float g_h0[N_NODES * 32];
__device__ float g_h1[N_NODES * 64];
__device__ float g_h2[N_NODES * 64];
__device__ int   g_cnt[N_NODES];        // in-degree
__device__ int   g_rs[N_NODES];         // CSR row start
__device__ int   g_cur[N_NODES];        // fill cursors
__device__ int   g_adj[N_EDGES];        // CSR adjacency (src per dst)
__device__ int   g_bsum[NB_SCAN + 8];
__device__ int   g_lo[N_GRAPHS + 1];

// ---------------- CSR build ----------------
__global__ void k_zero_cnt() {
    int i = blockIdx.x * blockDim.x + threadIdx.x;
    if (i < N_NODES) g_cnt[i] = 0;
}

__global__ void k_hist(const int* __restrict__ dst) {
    int e = blockIdx.x * blockDim.x + threadIdx.x;
    if (e < N_EDGES) atomicAdd(&g_cnt[dst[e]], 1);
}

__global__ void k_scan1() {
    __shared__ int wsum[8];
    int b = blockIdx.x, t = threadIdx.x;
    int lane = t & 31, w = t >> 5;
    int base = b * 1024 + t * 4;
    int v[4];
#pragma unroll
    for (int q = 0; q < 4; q++) v[q] = (base + q < N_NODES) ? g_cnt[base + q] : 0;
    int tot = v[0] + v[1] + v[2] + v[3];
    int sc = tot;
#pragma unroll
    for (int o = 1; o < 32; o <<= 1) {
        int x = __shfl_up_sync(0xffffffffu, sc, o);
        if (lane >= o) sc += x;
    }
    if (lane == 31) wsum[w] = sc;
    __syncthreads();
    if (t == 0) {
        int r = 0;
#pragma unroll
        for (int i = 0; i < 8; i++) { int x = wsum[i]; wsum[i] = r; r += x; }
        g_bsum[b] = r;
    }
    __syncthreads();
    int run = wsum[w] + (sc - tot);
#pragma unroll
    for (int q = 0; q < 4; q++) {
        if (base + q < N_NODES) g_rs[base + q] = run;
        run += v[q];
    }
}

__global__ void k_scan2() {
    __shared__ int sb[NB_SCAN];
    int t = threadIdx.x;
    if (t < NB_SCAN) sb[t] = g_bsum[t];
    __syncthreads();
    if (t == 0) {
        int r = 0;
        for (int i = 0; i < NB_SCAN; i++) { int x = sb[i]; sb[i] = r; r += x; }
    }
    __syncthreads();
    if (t < NB_SCAN) g_bsum[t] = sb[t];
}

__global__ void k_scan3() {
    int i = blockIdx.x * blockDim.x + threadIdx.x;
    if (i >= N_NODES) return;
    int v = g_rs[i] + g_bsum[i >> 10];
    g_rs[i] = v;
    g_cur[i] = v;
}

__global__ void k_fill(const int* __restrict__ src, const int* __restrict__ dst) {
    int e = blockIdx.x * blockDim.x + threadIdx.x;
    if (e >= N_EDGES) return;
    int d = dst[e];
    int pos = atomicAdd(&g_cur[d], 1);
    g_adj[pos] = src[e];
}

__global__ void k_bounds(const int* __restrict__ batch) {
    int g = blockIdx.x * blockDim.x + threadIdx.x;
    if (g > N_GRAPHS) return;
    int lo = 0, hi = N_NODES;
    while (lo < hi) {
        int m = (lo + hi) >> 1;
        if (batch[m] < g) lo = m + 1; else hi = m;
    }
    g_lo[g] = lo;
}

// ---------------- pre: h0 = relu(x @ pre_w + pre_b) ----------------
__global__ void k_pre(const float* __restrict__ x,
                      const float* __restrict__ w,
                      const float* __restrict__ b) {
    __shared__ float sw[5 * 32];
    __shared__ float sb[32];
    int t = threadIdx.x;
    if (t < 160) sw[t] = w[t];
    if (t < 32)  sb[t] = b[t];
    __syncthreads();
    int n = blockIdx.x * blockDim.x + t;
    if (n >= N_NODES) return;
    float xi[5];
#pragma unroll
    for (int i = 0; i < 5; i++) xi[i] = x[n * 5 + i];
    float4* outp = (float4*)&g_h0[n * 32];
#pragma unroll
    for (int j4 = 0; j4 < 8; j4++) {
        float4 v;
        float* vv = (float*)&v;
#pragma unroll
        for (int q = 0; q < 4; q++) {
            int j = j4 * 4 + q;
            float s = sb[j];
#pragma unroll
            for (int i = 0; i < 5; i++) s += xi[i] * sw[i * 32 + j];
            vv[q] = fmaxf(s, 0.f);
        }
        outp[j4] = v;
    }
}

// ---------------- conv1 fused: 4 nodes/warp, LDS-broadcast GEMM ----------
// v = [a(32); h(32)], W = [Wl; Wr] (64x64). out = v @ W, L2 norm, relu.
__global__ void __launch_bounds__(256) k_conv1(const float* __restrict__ wl,
                                               const float* __restrict__ bl,
                                               const float* __restrict__ wr) {
    __shared__ float sw[64 * 64];          // rows 0..31 Wl, 32..63 Wr
    __shared__ float sv[8][4][64];
    __shared__ float sb[64];
    int t = threadIdx.x;
    for (int i = t; i < 2048; i += 256) { sw[i] = wl[i]; sw[2048 + i] = wr[i]; }
    if (t < 64) sb[t] = bl[t];
    __syncthreads();
    int lane = t & 31, warp = t >> 5;
    int wg = blockIdx.x * 8 + warp;
    int nstride = gridDim.x * 8 * 4;
    for (int nb = wg * 4; nb < N_NODES; nb += nstride) {
#pragma unroll
        for (int g = 0; g < 4; g++) {
            int n = nb + g;
            if (n >= N_NODES) break;
            int rs = g_rs[n], d = g_cnt[n];
            float s0 = 0.f, s1 = 0.f, s2 = 0.f, s3 = 0.f;
            for (int j = 0; j < d; j += 32) {
                int chunk = min(32, d - j);
                int idx = (lane < chunk) ? g_adj[rs + j + lane] : 0;
                int q = 0;
                for (; q + 3 < chunk; q += 4) {
                    int n0 = __shfl_sync(0xffffffffu, idx, q);
                    int n1 = __shfl_sync(0xffffffffu, idx, q + 1);
                    int n2 = __shfl_sync(0xffffffffu, idx, q + 2);
                    int n3 = __shfl_sync(0xffffffffu, idx, q + 3);
                    s0 += g_h0[n0 * 32 + lane];
                    s1 += g_h0[n1 * 32 + lane];
                    s2 += g_h0[n2 * 32 + lane];
                    s3 += g_h0[n3 * 32 + lane];
                }
                for (; q < chunk; q++) {
                    int n0 = __shfl_sync(0xffffffffu, idx, q);
                    s0 += g_h0[n0 * 32 + lane];
                }
            }
            float inv = d > 0 ? 1.0f / (float)d : 0.0f;
            sv[warp][g][lane]      = (s0 + s1 + s2 + s3) * inv;
            sv[warp][g][32 + lane] = g_h0[n * 32 + lane];
        }
        __syncwarp();
        // combine: lane owns feats 2*lane, 2*lane+1
        float2 bias = *(float2*)&sb[2 * lane];
        float2 o[4];
#pragma unroll
        for (int g = 0; g < 4; g++) o[g] = bias;
#pragma unroll 4
        for (int k = 0; k < 64; k += 2) {
            float2 w0 = *(float2*)&sw[k * 64 + 2 * lane];
            float2 w1 = *(float2*)&sw[(k + 1) * 64 + 2 * lane];
#pragma unroll
            for (int g = 0; g < 4; g++) {
                float2 v = *(float2*)&sv[warp][g][k];
                o[g].x += v.x * w0.x + v.y * w1.x;
                o[g].y += v.x * w0.y + v.y * w1.y;
            }
        }
#pragma unroll
        for (int g = 0; g < 4; g++) {
            int n = nb + g;
            if (n >= N_NODES) break;
            float ss = o[g].x * o[g].x + o[g].y * o[g].y;
#pragma unroll
            for (int ofs = 16; ofs; ofs >>= 1) ss += __shfl_xor_sync(0xffffffffu, ss, ofs);
            float in2 = 1.0f / fmaxf(sqrtf(ss), 1e-12f);
            float2 r = make_float2(fmaxf(o[g].x * in2, 0.f), fmaxf(o[g].y * in2, 0.f));
            *(float2*)&g_h1[n * 64 + 2 * lane] = r;
        }
        __syncwarp();
    }
}

// ---------------- conv2 fused: 4 nodes/warp ----------------
// v = [a(64); h(64)], W = [Wl; Wr] (128x64)
__global__ void __launch_bounds__(256) k_conv2(const float* __restrict__ wl,
                                               const float* __restrict__ bl,
                                               const float* __restrict__ wr) {
    __shared__ float sw[128 * 64];
    __shared__ float sv[8][4][128];
    __shared__ float sb[64];
    int t = threadIdx.x;
    for (int i = t; i < 4096; i += 256) { sw[i] = wl[i]; sw[4096 + i] = wr[i]; }
    if (t < 64) sb[t] = bl[t];
    __syncthreads();
    int lane = t & 31, warp = t >> 5;
    int wg = blockIdx.x * 8 + warp;
    int nstride = gridDim.x * 8 * 4;
    for (int nb = wg * 4; nb < N_NODES; nb += nstride) {
#pragma unroll
        for (int g = 0; g < 4; g++) {
            int n = nb + g;
            if (n >= N_NODES) break;
            int rs = g_rs[n], d = g_cnt[n];
            float s0 = 0.f, s1 = 0.f, s2 = 0.f, s3 = 0.f;
            for (int j = 0; j < d; j += 32) {
                int chunk = min(32, d - j);
                int idx = (lane < chunk) ? g_adj[rs + j + lane] : 0;
                int q = 0;
                for (; q + 3 < chunk; q += 4) {
                    int n0 = __shfl_sync(0xffffffffu, idx, q);
                    int n1 = __shfl_sync(0xffffffffu, idx, q + 1);
                    int n2 = __shfl_sync(0xffffffffu, idx, q + 2);
                    int n3 = __shfl_sync(0xffffffffu, idx, q + 3);
                    s0 += g_h1[n0 * 64 + lane];
                    s1 += g_h1[n0 * 64 + 32 + lane];
                    s2 += g_h1[n1 * 64 + lane];
                    s3 += g_h1[n1 * 64 + 32 + lane];
                    s0 += g_h1[n2 * 64 + lane];
                    s1 += g_h1[n2 * 64 + 32 + lane];
                    s2 += g_h1[n3 * 64 + lane];
                    s3 += g_h1[n3 * 64 + 32 + lane];
                }
                for (; q < chunk; q++) {
                    int n0 = __shfl_sync(0xffffffffu, idx, q);
                    s0 += g_h1[n0 * 64 + lane];
                    s1 += g_h1[n0 * 64 + 32 + lane];
                }
            }
            float inv = d > 0 ? 1.0f / (float)d : 0.0f;
            sv[warp][g][lane]      = (s0 + s2) * inv;
            sv[warp][g][32 + lane] = (s1 + s3) * inv;
            sv[warp][g][64 + lane] = g_h1[n * 64 + lane];
            sv[warp][g][96 + lane] = g_h1[n * 64 + 32 + lane];
        }
        __syncwarp();
        float2 bias = *(float2*)&sb[2 * lane];
        float2 o[4];
#pragma unroll
        for (int g = 0; g < 4; g++) o[g] = bias;
#pragma unroll 4
        for (int k = 0; k < 128; k += 2) {
            float2 w0 = *(float2*)&sw[k * 64 + 2 * lane];
            float2 w1 = *(float2*)&sw[(k + 1) * 64 + 2 * lane];
#pragma unroll
            for (int g = 0; g < 4; g++) {
                float2 v = *(float2*)&sv[warp][g][k];
                o[g].x += v.x * w0.x + v.y * w1.x;
                o[g].y += v.x * w0.y + v.y * w1.y;
            }
        }
#pragma unroll
        for (int g = 0; g < 4; g++) {
            int n = nb + g;
            if (n >= N_NODES) break;
            float ss = o[g].x * o[g].x + o[g].y * o[g].y;
#pragma unroll
            for (int ofs = 16; ofs; ofs >>= 1) ss += __shfl_xor_sync(0xffffffffu, ss, ofs);
            float in2 = 1.0f / fmaxf(sqrtf(ss), 1e-12f);
            float2 r = make_float2(fmaxf(o[g].x * in2, 0.f), fmaxf(o[g].y * in2, 0.f));
            *(float2*)&g_h2[n * 64 + 2 * lane] = r;
        }
        __syncwarp();
    }
}

// ---------------- head: contiguous-range mean pool + MLP ----------------
__global__ void k_head(const float* __restrict__ p1w, const float* __restrict__ p1b,
                       const float* __restrict__ p2w, const float* __restrict__ p2b,
                       const float* __restrict__ ow,  const float* __restrict__ ob,
                       float* __restrict__ out) {
    __shared__ float part[4 * 64];
    __shared__ float sg[64], t1[64], t2[16];
    int g = blockIdx.x, t = threadIdx.x;
    int lo = g_lo[g], hi = g_lo[g + 1];
    int f = t & 63, r = t >> 6;
    float s = 0.f;
    for (int n = lo + r; n < hi; n += 4) s += g_h2[n * 64 + f];
    part[r * 64 + f] = s;
    __syncthreads();
    if (t < 64) {
        float tot = part[t] + part[64 + t] + part[128 + t] + part[192 + t];
        float cnt = (float)(hi - lo);
        sg[t] = tot / fmaxf(cnt, 1.0f);
    }
    __syncthreads();
    if (t < 64) {
        float s1 = p1b[t];
#pragma unroll 8
        for (int k = 0; k < 64; k++) s1 += sg[k] * p1w[k * 64 + t];
        t1[t] = fmaxf(s1, 0.f);
    }
    __syncthreads();
    if (t < 16) {
        float s2 = p2b[t];
#pragma unroll 8
        for (int k = 0; k < 64; k++) s2 += t1[k] * p2w[k * 16 + t];
        t2[t] = fmaxf(s2, 0.f);
    }
    __syncthreads();
    if (t == 0) {
        float o = ob[0];
#pragma unroll
        for (int k = 0; k < 16; k++) o += t2[k] * ow[k];
        out[g] = o;
    }
}

// ---------------- launch ----------------
extern "C" void kernel_launch(void* const* d_in, const int* in_sizes, int n_in,
                              void* d_out, int out_size) {
    const float* x     = (const float*)d_in[0];
    const int*   ei    = (const int*)d_in[1];
    const int*   batch = (const int*)d_in[2];
    int base = (n_in >= 18 && in_sizes[3] == 1) ? 4 : 3;
    const float* pre_w = (const float*)d_in[base + 0];
    const float* pre_b = (const float*)d_in[base + 1];
    const float* c1_wl = (const float*)d_in[base + 2];
    const float* c1_bl = (const float*)d_in[base + 3];
    const float* c1_wr = (const float*)d_in[base + 4];
    const float* c2_wl = (const float*)d_in[base + 5];
    const float* c2_bl = (const float*)d_in[base + 6];
    const float* c2_wr = (const float*)d_in[base + 7];
    const float* p1_w  = (const float*)d_in[base + 8];
    const float* p1_b  = (const float*)d_in[base + 9];
    const float* p2_w  = (const float*)d_in[base + 10];
    const float* p2_b  = (const float*)d_in[base + 11];
    const float* o_w   = (const float*)d_in[base + 12];
    const float* o_b   = (const float*)d_in[base + 13];

    const int* src = ei;
    const int* dst = ei + N_EDGES;
    float* out = (float*)d_out;

    const int T = 256;
    k_zero_cnt<<<(N_NODES + T - 1) / T, T>>>();
    k_pre<<<(N_NODES + T - 1) / T, T>>>(x, pre_w, pre_b);
    k_hist<<<(N_EDGES + T - 1) / T, T>>>(dst);
    k_scan1<<<NB_SCAN, 256>>>();
    k_scan2<<<1, 128>>>();
    k_scan3<<<(N_NODES + T - 1) / T, T>>>();
    k_fill<<<(N_EDGES + T - 1) / T, T>>>(src, dst);
    k_bounds<<<3, 256>>>(batch);

    k_conv1<<<1184, 256>>>(c1_wl, c1_bl, c1_wr);
    k_conv2<<<592, 256>>>(c2_wl, c2_bl, c2_wr);

    k_head<<<N_GRAPHS, 256>>>(p1_w, p1_b, p2_w, p2_b, o_w, o_b, out);
    (void)out_size;
}

// round 6
// speedup vs baseline: 1.7922x; 1.0585x over previous
#include <cuda_runtime.h>
#include <cuda_fp16.h>

#define N_NODES  100000
#define N_EDGES  1600000
#define N_GRAPHS 512
#define NB_SCAN  ((N_NODES + 1023) / 1024)   // 98

// ---------------- device scratch (no allocations allowed) ----------------
__device__ float   g_h0[N_NODES * 32];
__device__ __half2 g_h1h[N_NODES * 32];     // h1 as fp16 pairs (feats 2l,2l+1)
__device__ float   g_h2[N_NODES * 64];
__device__ int     g_cnt[N_NODES];
__device__ int     g_rs[N_NODES];
__device__ int     g_cur[N_NODES];
__device__ int     g_adj[N_EDGES];
__device__ int     g_bsum[NB_SCAN + 8];
__device__ int     g_lo[N_GRAPHS + 1];

// ---------------- CSR build ----------------
__global__ void k_hist(const int* __restrict__ dst) {
    int i = blockIdx.x * blockDim.x + threadIdx.x;
    int e4 = i * 4;
    if (e4 + 3 < N_EDGES) {
        int4 d = *(const int4*)&dst[e4];
        atomicAdd(&g_cnt[d.x], 1);
        atomicAdd(&g_cnt[d.y], 1);
        atomicAdd(&g_cnt[d.z], 1);
        atomicAdd(&g_cnt[d.w], 1);
    } else if (e4 < N_EDGES) {
        for (int e = e4; e < N_EDGES; e++) atomicAdd(&g_cnt[dst[e]], 1);
    }
}

__global__ void k_scan1() {
    __shared__ int wsum[8];
    int b = blockIdx.x, t = threadIdx.x;
    int lane = t & 31, w = t >> 5;
    int base = b * 1024 + t * 4;
    int v[4];
#pragma unroll
    for (int q = 0; q < 4; q++) v[q] = (base + q < N_NODES) ? g_cnt[base + q] : 0;
    int tot = v[0] + v[1] + v[2] + v[3];
    int sc = tot;
#pragma unroll
    for (int o = 1; o < 32; o <<= 1) {
        int x = __shfl_up_sync(0xffffffffu, sc, o);
        if (lane >= o) sc += x;
    }
    if (lane == 31) wsum[w] = sc;
    __syncthreads();
    if (t == 0) {
        int r = 0;
#pragma unroll
        for (int i = 0; i < 8; i++) { int x = wsum[i]; wsum[i] = r; r += x; }
        g_bsum[b] = r;
    }
    __syncthreads();
    int run = wsum[w] + (sc - tot);
#pragma unroll
    for (int q = 0; q < 4; q++) {
        if (base + q < N_NODES) g_rs[base + q] = run;
        run += v[q];
    }
}

// block 0: scan of block sums; blocks 1..3: graph boundary binary search
__global__ void k_scan2_bounds(const int* __restrict__ batch) {
    if (blockIdx.x == 0) {
        __shared__ int sb[NB_SCAN];
        int t = threadIdx.x;
        if (t < NB_SCAN) sb[t] = g_bsum[t];
        __syncthreads();
        if (t == 0) {
            int r = 0;
            for (int i = 0; i < NB_SCAN; i++) { int x = sb[i]; sb[i] = r; r += x; }
        }
        __syncthreads();
        if (t < NB_SCAN) g_bsum[t] = sb[t];
    } else {
        int g = (blockIdx.x - 1) * 256 + threadIdx.x;
        if (g > N_GRAPHS) return;
        int lo = 0, hi = N_NODES;
        while (lo < hi) {
            int m = (lo + hi) >> 1;
            if (batch[m] < g) lo = m + 1; else hi = m;
        }
        g_lo[g] = lo;
    }
}

__global__ void k_scan3() {
    int i = blockIdx.x * blockDim.x + threadIdx.x;
    if (i >= N_NODES) return;
    int v = g_rs[i] + g_bsum[i >> 10];
    g_rs[i] = v;
    g_cur[i] = v;
}

__global__ void k_fill(const int* __restrict__ src, const int* __restrict__ dst) {
    int e = blockIdx.x * blockDim.x + threadIdx.x;
    if (e >= N_EDGES) return;
    int d = dst[e];
    int pos = atomicAdd(&g_cur[d], 1);
    g_adj[pos] = src[e];
}

// ---------------- pre: h0 = relu(x @ pre_w + pre_b); also zero g_cnt -----
__global__ void k_pre(const float* __restrict__ x,
                      const float* __restrict__ w,
                      const float* __restrict__ b) {
    __shared__ float sw[5 * 32];
    __shared__ float sb[32];
    int t = threadIdx.x;
    if (t < 160) sw[t] = w[t];
    if (t < 32)  sb[t] = b[t];
    __syncthreads();
    int n = blockIdx.x * blockDim.x + t;
    if (n >= N_NODES) return;
    g_cnt[n] = 0;
    float xi[5];
#pragma unroll
    for (int i = 0; i < 5; i++) xi[i] = x[n * 5 + i];
    float4* outp = (float4*)&g_h0[n * 32];
#pragma unroll
    for (int j4 = 0; j4 < 8; j4++) {
        float4 v;
        float* vv = (float*)&v;
#pragma unroll
        for (int q = 0; q < 4; q++) {
            int j = j4 * 4 + q;
            float s = sb[j];
#pragma unroll
            for (int i = 0; i < 5; i++) s += xi[i] * sw[i * 32 + j];
            vv[q] = fmaxf(s, 0.f);
        }
        outp[j4] = v;
    }
}

// ---------------- conv1 fused: gather fp32 h0, output fp16 h1 ------------
__global__ void __launch_bounds__(256) k_conv1(const float* __restrict__ wl,
                                               const float* __restrict__ bl,
                                               const float* __restrict__ wr) {
    __shared__ float sw[64 * 64];          // rows 0..31 Wl, 32..63 Wr
    __shared__ float sv[8][4][64];
    __shared__ float sb[64];
    int t = threadIdx.x;
    for (int i = t; i < 2048; i += 256) { sw[i] = wl[i]; sw[2048 + i] = wr[i]; }
    if (t < 64) sb[t] = bl[t];
    __syncthreads();
    int lane = t & 31, warp = t >> 5;
    int wg = blockIdx.x * 8 + warp;
    int nstride = gridDim.x * 8 * 4;
    for (int nb = wg * 4; nb < N_NODES; nb += nstride) {
#pragma unroll
        for (int g = 0; g < 4; g++) {
            int n = nb + g;
            if (n >= N_NODES) break;
            int rs = g_rs[n], d = g_cnt[n];
            float s0 = 0.f, s1 = 0.f, s2 = 0.f, s3 = 0.f;
            for (int j = 0; j < d; j += 32) {
                int chunk = min(32, d - j);
                int idx = (lane < chunk) ? g_adj[rs + j + lane] : 0;
                int q = 0;
                for (; q + 3 < chunk; q += 4) {
                    int n0 = __shfl_sync(0xffffffffu, idx, q);
                    int n1 = __shfl_sync(0xffffffffu, idx, q + 1);
                    int n2 = __shfl_sync(0xffffffffu, idx, q + 2);
                    int n3 = __shfl_sync(0xffffffffu, idx, q + 3);
                    s0 += g_h0[n0 * 32 + lane];
                    s1 += g_h0[n1 * 32 + lane];
                    s2 += g_h0[n2 * 32 + lane];
                    s3 += g_h0[n3 * 32 + lane];
                }
                for (; q < chunk; q++) {
                    int n0 = __shfl_sync(0xffffffffu, idx, q);
                    s0 += g_h0[n0 * 32 + lane];
                }
            }
            float inv = d > 0 ? 1.0f / (float)d : 0.0f;
            sv[warp][g][lane]      = (s0 + s1 + s2 + s3) * inv;
            sv[warp][g][32 + lane] = g_h0[n * 32 + lane];
        }
        __syncwarp();
        float2 bias = *(float2*)&sb[2 * lane];
        float2 o[4];
#pragma unroll
        for (int g = 0; g < 4; g++) o[g] = bias;
#pragma unroll 4
        for (int k = 0; k < 64; k += 2) {
            float2 w0 = *(float2*)&sw[k * 64 + 2 * lane];
            float2 w1 = *(float2*)&sw[(k + 1) * 64 + 2 * lane];
#pragma unroll
            for (int g = 0; g < 4; g++) {
                float2 v = *(float2*)&sv[warp][g][k];
                o[g].x += v.x * w0.x + v.y * w1.x;
                o[g].y += v.x * w0.y + v.y * w1.y;
            }
        }
#pragma unroll
        for (int g = 0; g < 4; g++) {
            int n = nb + g;
            if (n >= N_NODES) break;
            float ss = o[g].x * o[g].x + o[g].y * o[g].y;
#pragma unroll
            for (int ofs = 16; ofs; ofs >>= 1) ss += __shfl_xor_sync(0xffffffffu, ss, ofs);
            float in2 = 1.0f / fmaxf(sqrtf(ss), 1e-12f);
            g_h1h[n * 32 + lane] =
                __floats2half2_rn(fmaxf(o[g].x * in2, 0.f), fmaxf(o[g].y * in2, 0.f));
        }
        __syncwarp();
    }
}

// ---------------- conv2 fused: gather fp16 h1 (128B rows), fp32 math -----
__global__ void __launch_bounds__(256) k_conv2(const float* __restrict__ wl,
                                               const float* __restrict__ bl,
                                               const float* __restrict__ wr) {
    __shared__ float sw[128 * 64];
    __shared__ float sv[8][4][128];
    __shared__ float sb[64];
    int t = threadIdx.x;
    for (int i = t; i < 4096; i += 256) { sw[i] = wl[i]; sw[4096 + i] = wr[i]; }
    if (t < 64) sb[t] = bl[t];
    __syncthreads();
    int lane = t & 31, warp = t >> 5;
    int wg = blockIdx.x * 8 + warp;
    int nstride = gridDim.x * 8 * 4;
    for (int nb = wg * 4; nb < N_NODES; nb += nstride) {
#pragma unroll
        for (int g = 0; g < 4; g++) {
            int n = nb + g;
            if (n >= N_NODES) break;
            int rs = g_rs[n], d = g_cnt[n];
            float a0 = 0.f, b0 = 0.f, a1 = 0.f, b1 = 0.f;
            for (int j = 0; j < d; j += 32) {
                int chunk = min(32, d - j);
                int idx = (lane < chunk) ? g_adj[rs + j + lane] : 0;
                int q = 0;
                for (; q + 3 < chunk; q += 4) {
                    int n0 = __shfl_sync(0xffffffffu, idx, q);
                    int n1 = __shfl_sync(0xffffffffu, idx, q + 1);
                    int n2 = __shfl_sync(0xffffffffu, idx, q + 2);
                    int n3 = __shfl_sync(0xffffffffu, idx, q + 3);
                    float2 f0 = __half22float2(g_h1h[n0 * 32 + lane]);
                    float2 f1 = __half22float2(g_h1h[n1 * 32 + lane]);
                    float2 f2 = __half22float2(g_h1h[n2 * 32 + lane]);
                    float2 f3 = __half22float2(g_h1h[n3 * 32 + lane]);
                    a0 += f0.x; b0 += f0.y;
                    a1 += f1.x; b1 += f1.y;
                    a0 += f2.x; b0 += f2.y;
                    a1 += f3.x; b1 += f3.y;
                }
                for (; q < chunk; q++) {
                    int n0 = __shfl_sync(0xffffffffu, idx, q);
                    float2 f0 = __half22float2(g_h1h[n0 * 32 + lane]);
                    a0 += f0.x; b0 += f0.y;
                }
            }
            float inv = d > 0 ? 1.0f / (float)d : 0.0f;
            *(float2*)&sv[warp][g][2 * lane] =
                make_float2((a0 + a1) * inv, (b0 + b1) * inv);
            float2 root = __half22float2(g_h1h[n * 32 + lane]);
            *(float2*)&sv[warp][g][64 + 2 * lane] = root;
        }
        __syncwarp();
        float2 bias = *(float2*)&sb[2 * lane];
        float2 o[4];
#pragma unroll
        for (int g = 0; g < 4; g++) o[g] = bias;
#pragma unroll 4
        for (int k = 0; k < 128; k += 2) {
            float2 w0 = *(float2*)&sw[k * 64 + 2 * lane];
            float2 w1 = *(float2*)&sw[(k + 1) * 64 + 2 * lane];
#pragma unroll
            for (int g = 0; g < 4; g++) {
                float2 v = *(float2*)&sv[warp][g][k];
                o[g].x += v.x * w0.x + v.y * w1.x;
                o[g].y += v.x * w0.y + v.y * w1.y;
            }
        }
#pragma unroll
        for (int g = 0; g < 4; g++) {
            int n = nb + g;
            if (n >= N_NODES) break;
            float ss = o[g].x * o[g].x + o[g].y * o[g].y;
#pragma unroll
            for (int ofs = 16; ofs; ofs >>= 1) ss += __shfl_xor_sync(0xffffffffu, ss, ofs);
            float in2 = 1.0f / fmaxf(sqrtf(ss), 1e-12f);
            float2 r = make_float2(fmaxf(o[g].x * in2, 0.f), fmaxf(o[g].y * in2, 0.f));
            *(float2*)&g_h2[n * 64 + 2 * lane] = r;
        }
        __syncwarp();
    }
}

// ---------------- head: contiguous-range mean pool + MLP ----------------
__global__ void k_head(const float* __restrict__ p1w, const float* __restrict__ p1b,
                       const float* __restrict__ p2w, const float* __restrict__ p2b,
                       const float* __restrict__ ow,  const float* __restrict__ ob,
                       float* __restrict__ out) {
    __shared__ float part[4 * 64];
    __shared__ float sg[64], t1[64], t2[16];
    int g = blockIdx.x, t = threadIdx.x;
    int lo = g_lo[g], hi = g_lo[g + 1];
    int f = t & 63, r = t >> 6;
    float s = 0.f;
    for (int n = lo + r; n < hi; n += 4) s += g_h2[n * 64 + f];
    part[r * 64 + f] = s;
    __syncthreads();
    if (t < 64) {
        float tot = part[t] + part[64 + t] + part[128 + t] + part[192 + t];
        float cnt = (float)(hi - lo);
        sg[t] = tot / fmaxf(cnt, 1.0f);
    }
    __syncthreads();
    if (t < 64) {
        float s1 = p1b[t];
#pragma unroll 8
        for (int k = 0; k < 64; k++) s1 += sg[k] * p1w[k * 64 + t];
        t1[t] = fmaxf(s1, 0.f);
    }
    __syncthreads();
    if (t < 16) {
        float s2 = p2b[t];
#pragma unroll 8
        for (int k = 0; k < 64; k++) s2 += t1[k] * p2w[k * 16 + t];
        t2[t] = fmaxf(s2, 0.f);
    }
    __syncthreads();
    if (t == 0) {
        float o = ob[0];
#pragma unroll
        for (int k = 0; k < 16; k++) o += t2[k] * ow[k];
        out[g] = o;
    }
}

// ---------------- launch ----------------
extern "C" void kernel_launch(void* const* d_in, const int* in_sizes, int n_in,
                              void* d_out, int out_size) {
    const float* x     = (const float*)d_in[0];
    const int*   ei    = (const int*)d_in[1];
    const int*   batch = (const int*)d_in[2];
    int base = (n_in >= 18 && in_sizes[3] == 1) ? 4 : 3;
    const float* pre_w = (const float*)d_in[base + 0];
    const float* pre_b = (const float*)d_in[base + 1];
    const float* c1_wl = (const float*)d_in[base + 2];
    const float* c1_bl = (const float*)d_in[base + 3];
    const float* c1_wr = (const float*)d_in[base + 4];
    const float* c2_wl = (const float*)d_in[base + 5];
    const float* c2_bl = (const float*)d_in[base + 6];
    const float* c2_wr = (const float*)d_in[base + 7];
    const float* p1_w  = (const float*)d_in[base + 8];
    const float* p1_b  = (const float*)d_in[base + 9];
    const float* p2_w  = (const float*)d_in[base + 10];
    const float* p2_b  = (const float*)d_in[base + 11];
    const float* o_w   = (const float*)d_in[base + 12];
    const float* o_b   = (const float*)d_in[base + 13];

    const int* src = ei;
    const int* dst = ei + N_EDGES;
    float* out = (float*)d_out;

    const int T = 256;
    k_pre<<<(N_NODES + T - 1) / T, T>>>(x, pre_w, pre_b);        // also zeroes g_cnt
    k_hist<<<(N_EDGES / 4 + T - 1) / T, T>>>(dst);
    k_scan1<<<NB_SCAN, 256>>>();
    k_scan2_bounds<<<4, 256>>>(batch);
    k_scan3<<<(N_NODES + T - 1) / T, T>>>();
    k_fill<<<(N_EDGES + T - 1) / T, T>>>(src, dst);

    k_conv1<<<1184, 256>>>(c1_wl, c1_bl, c1_wr);
    k_conv2<<<592, 256>>>(c2_wl, c2_bl, c2_wr);

    k_head<<<N_GRAPHS, 256>>>(p1_w, p1_b, p2_w, p2_b, o_w, o_b, out);
    (void)out_size;
}

// round 9
// speedup vs baseline: 1.8926x; 1.0560x over previous
#include <cuda_runtime.h>
#include <cuda_fp16.h>

#define N_NODES  100000
#define N_EDGES  1600000
#define N_GRAPHS 512
#define NB_SCAN  ((N_NODES + 1023) / 1024)   // 98

// ---------------- device scratch (no allocations allowed) ----------------
__device__ __half2 g_h0h[N_NODES * 16];     // h0 fp16 pairs (64B/row)
__device__ __half2 g_h1h[N_NODES * 32];     // h1 fp16 pairs (128B/row)
__device__ float   g_h2[N_NODES * 64];
__device__ int     g_cnt[N_NODES];
__device__ int     g_rs[N_NODES];
__device__ int     g_cur[N_NODES];
__device__ int     g_adj[N_EDGES];
__device__ int     g_bsum[NB_SCAN + 8];
__device__ int     g_lo[N_GRAPHS + 1];

// ---------------- CSR build ----------------
__global__ void k_hist(const int* __restrict__ dst) {
    int i = blockIdx.x * blockDim.x + threadIdx.x;
    int e4 = i * 4;
    if (e4 + 3 < N_EDGES) {
        int4 d = *(const int4*)&dst[e4];
        atomicAdd(&g_cnt[d.x], 1);
        atomicAdd(&g_cnt[d.y], 1);
        atomicAdd(&g_cnt[d.z], 1);
        atomicAdd(&g_cnt[d.w], 1);
    } else if (e4 < N_EDGES) {
        for (int e = e4; e < N_EDGES; e++) atomicAdd(&g_cnt[dst[e]], 1);
    }
}

__global__ void k_scan1() {
    __shared__ int wsum[8];
    int b = blockIdx.x, t = threadIdx.x;
    int lane = t & 31, w = t >> 5;
    int base = b * 1024 + t * 4;
    int v[4];
#pragma unroll
    for (int q = 0; q < 4; q++) v[q] = (base + q < N_NODES) ? g_cnt[base + q] : 0;
    int tot = v[0] + v[1] + v[2] + v[3];
    int sc = tot;
#pragma unroll
    for (int o = 1; o < 32; o <<= 1) {
        int x = __shfl_up_sync(0xffffffffu, sc, o);
        if (lane >= o) sc += x;
    }
    if (lane == 31) wsum[w] = sc;
    __syncthreads();
    if (t == 0) {
        int r = 0;
#pragma unroll
        for (int i = 0; i < 8; i++) { int x = wsum[i]; wsum[i] = r; r += x; }
        g_bsum[b] = r;
    }
    __syncthreads();
    int run = wsum[w] + (sc - tot);
#pragma unroll
    for (int q = 0; q < 4; q++) {
        if (base + q < N_NODES) g_rs[base + q] = run;
        run += v[q];
    }
}

// single block: exclusive scan of block sums
__global__ void k_scan2() {
    __shared__ int sb[NB_SCAN];
    int t = threadIdx.x;
    if (t < NB_SCAN) sb[t] = g_bsum[t];
    __syncthreads();
    if (t == 0) {
        int r = 0;
        for (int i = 0; i < NB_SCAN; i++) { int x = sb[i]; sb[i] = r; r += x; }
    }
    __syncthreads();
    if (t < NB_SCAN) g_bsum[t] = sb[t];
}

// add block offsets, init cursors, detect graph boundaries (batch sorted)
__global__ void k_scan3(const int* __restrict__ batch) {
    int i = blockIdx.x * blockDim.x + threadIdx.x;
    if (i >= N_NODES) return;
    int v = g_rs[i] + g_bsum[i >> 10];
    g_rs[i] = v;
    g_cur[i] = v;
    int b = batch[i];
    int bn = (i + 1 < N_NODES) ? batch[i + 1] : N_GRAPHS;
    if (i == 0)
        for (int g = 0; g <= b; g++) g_lo[g] = 0;
    for (int g = b + 1; g <= bn; g++) g_lo[g] = i + 1;
}

__global__ void k_fill(const int* __restrict__ src, const int* __restrict__ dst) {
    int i = blockIdx.x * blockDim.x + threadIdx.x;
    int e4 = i * 4;
    if (e4 + 3 < N_EDGES) {
        int4 s = *(const int4*)&src[e4];
        int4 d = *(const int4*)&dst[e4];
        g_adj[atomicAdd(&g_cur[d.x], 1)] = s.x;
        g_adj[atomicAdd(&g_cur[d.y], 1)] = s.y;
        g_adj[atomicAdd(&g_cur[d.z], 1)] = s.z;
        g_adj[atomicAdd(&g_cur[d.w], 1)] = s.w;
    } else if (e4 < N_EDGES) {
        for (int e = e4; e < N_EDGES; e++)
            g_adj[atomicAdd(&g_cur[dst[e]], 1)] = src[e];
    }
}

// ---------------- pre: h0 = relu(x @ pre_w + pre_b) -> fp16; zero cnt ----
__global__ void k_pre(const float* __restrict__ x,
                      const float* __restrict__ w,
                      const float* __restrict__ b) {
    __shared__ float sw[5 * 32];
    __shared__ float sb[32];
    int t = threadIdx.x;
    if (t < 160) sw[t] = w[t];
    if (t < 32)  sb[t] = b[t];
    __syncthreads();
    int n = blockIdx.x * blockDim.x + t;
    if (n >= N_NODES) return;
    g_cnt[n] = 0;
    float xi[5];
#pragma unroll
    for (int i = 0; i < 5; i++) xi[i] = x[n * 5 + i];
    __half2 hv[16];
#pragma unroll
    for (int j2 = 0; j2 < 16; j2++) {
        float o0 = sb[2 * j2], o1 = sb[2 * j2 + 1];
#pragma unroll
        for (int i = 0; i < 5; i++) {
            o0 += xi[i] * sw[i * 32 + 2 * j2];
            o1 += xi[i] * sw[i * 32 + 2 * j2 + 1];
        }
        hv[j2] = __floats2half2_rn(fmaxf(o0, 0.f), fmaxf(o1, 0.f));
    }
    uint4* dstp = (uint4*)&g_h0h[n * 16];   // 16 half2 = 64B = 4 uint4
    dstp[0] = ((uint4*)hv)[0];
    dstp[1] = ((uint4*)hv)[1];
    dstp[2] = ((uint4*)hv)[2];
    dstp[3] = ((uint4*)hv)[3];
}

// ---------------- conv1: fp16 h0 gather (paired neighbors), fp16 h1 out --
__global__ void __launch_bounds__(256) k_conv1(const float* __restrict__ wl,
                                               const float* __restrict__ bl,
                                               const float* __restrict__ wr) {
    __shared__ float sw[64 * 64];          // rows 0..31 Wl, 32..63 Wr
    __shared__ float sv[8][4][64];
    __shared__ float sb[64];
    int t = threadIdx.x;
    for (int i = t; i < 2048; i += 256) { sw[i] = wl[i]; sw[2048 + i] = wr[i]; }
    if (t < 64) sb[t] = bl[t];
    __syncthreads();
    int lane = t & 31, warp = t >> 5;
    int l15 = lane & 15;
    bool hihalf = lane >= 16;
    int wg = blockIdx.x * 8 + warp;
    int nstride = gridDim.x * 8 * 4;
    for (int nb = wg * 4; nb < N_NODES; nb += nstride) {
#pragma unroll
        for (int g = 0; g < 4; g++) {
            int n = nb + g;
            if (n >= N_NODES) break;
            int rs = g_rs[n], d = g_cnt[n];
            float2 acc0 = make_float2(0.f, 0.f), acc1 = make_float2(0.f, 0.f);
            for (int j = 0; j < d; j += 32) {
                int chunk = min(32, d - j);
                int idx = (lane < chunk) ? g_adj[rs + j + lane] : 0;
                int q = 0;
                for (; q + 3 < chunk; q += 4) {
                    int nA = __shfl_sync(0xffffffffu, idx, q);
                    int nB = __shfl_sync(0xffffffffu, idx, q + 1);
                    int nC = __shfl_sync(0xffffffffu, idx, q + 2);
                    int nD = __shfl_sync(0xffffffffu, idx, q + 3);
                    int s0 = hihalf ? nB : nA;
                    int s1 = hihalf ? nD : nC;
                    float2 f0 = __half22float2(g_h0h[s0 * 16 + l15]);
                    float2 f1 = __half22float2(g_h0h[s1 * 16 + l15]);
                    acc0.x += f0.x; acc0.y += f0.y;
                    acc1.x += f1.x; acc1.y += f1.y;
                }
                for (; q + 1 < chunk; q += 2) {
                    int nA = __shfl_sync(0xffffffffu, idx, q);
                    int nB = __shfl_sync(0xffffffffu, idx, q + 1);
                    int s0 = hihalf ? nB : nA;
                    float2 f0 = __half22float2(g_h0h[s0 * 16 + l15]);
                    acc0.x += f0.x; acc0.y += f0.y;
                }
                if (q < chunk) {
                    int nA = __shfl_sync(0xffffffffu, idx, q);
                    if (!hihalf) {
                        float2 f0 = __half22float2(g_h0h[nA * 16 + l15]);
                        acc0.x += f0.x; acc0.y += f0.y;
                    }
                }
            }
            // merge the two half-warps
            acc0.x += acc1.x; acc0.y += acc1.y;
            acc0.x += __shfl_xor_sync(0xffffffffu, acc0.x, 16);
            acc0.y += __shfl_xor_sync(0xffffffffu, acc0.y, 16);
            float inv = d > 0 ? 1.0f / (float)d : 0.0f;
            if (!hihalf) {
                *(float2*)&sv[warp][g][2 * l15] =
                    make_float2(acc0.x * inv, acc0.y * inv);
                float2 root = __half22float2(g_h0h[n * 16 + l15]);
                *(float2*)&sv[warp][g][32 + 2 * l15] = root;
            }
        }
        __syncwarp();
        float2 bias = *(float2*)&sb[2 * lane];
        float2 o[4];
#pragma unroll
        for (int g = 0; g < 4; g++) o[g] = bias;
#pragma unroll 4
        for (int k = 0; k < 64; k += 2) {
            float2 w0 = *(float2*)&sw[k * 64 + 2 * lane];
            float2 w1 = *(float2*)&sw[(k + 1) * 64 + 2 * lane];
#pragma unroll
            for (int g = 0; g < 4; g++) {
                float2 v = *(float2*)&sv[warp][g][k];
                o[g].x += v.x * w0.x + v.y * w1.x;
                o[g].y += v.x * w0.y + v.y * w1.y;
            }
        }
#pragma unroll
        for (int g = 0; g < 4; g++) {
            int n = nb + g;
            if (n >= N_NODES) break;
            float ss = o[g].x * o[g].x + o[g].y * o[g].y;
#pragma unroll
            for (int ofs = 16; ofs; ofs >>= 1) ss += __shfl_xor_sync(0xffffffffu, ss, ofs);
            float in2 = 1.0f / fmaxf(sqrtf(ss), 1e-12f);
            g_h1h[n * 32 + lane] =
                __floats2half2_rn(fmaxf(o[g].x * in2, 0.f), fmaxf(o[g].y * in2, 0.f));
        }
        __syncwarp();
    }
}

// ---------------- conv2: fp16 h1 gather (128B rows), fp32 math -----------
__global__ void __launch_bounds__(256) k_conv2(const float* __restrict__ wl,
                                               const float* __restrict__ bl,
                                               const float* __restrict__ wr) {
    __shared__ float sw[128 * 64];
    __shared__ float sv[8][4][128];
    __shared__ float sb[64];
    int t = threadIdx.x;
    for (int i = t; i < 4096; i += 256) { sw[i] = wl[i]; sw[4096 + i] = wr[i]; }
    if (t < 64) sb[t] = bl[t];
    __syncthreads();
    int lane = t & 31, warp = t >> 5;
    int wg = blockIdx.x * 8 + warp;
    int nstride = gridDim.x * 8 * 4;
    for (int nb = wg * 4; nb < N_NODES; nb += nstride) {
#pragma unroll
        for (int g = 0; g < 4; g++) {
            int n = nb + g;
            if (n >= N_NODES) break;
            int rs = g_rs[n], d = g_cnt[n];
            float a0 = 0.f, b0 = 0.f, a1 = 0.f, b1 = 0.f;
            for (int j = 0; j < d; j += 32) {
                int chunk = min(32, d - j);
                int idx = (lane < chunk) ? g_adj[rs + j + lane] : 0;
                int q = 0;
                for (; q + 3 < chunk; q += 4) {
                    int n0 = __shfl_sync(0xffffffffu, idx, q);
                    int n1 = __shfl_sync(0xffffffffu, idx, q + 1);
                    int n2 = __shfl_sync(0xffffffffu, idx, q + 2);
                    int n3 = __shfl_sync(0xffffffffu, idx, q + 3);
                    float2 f0 = __half22float2(g_h1h[n0 * 32 + lane]);
                    float2 f1 = __half22float2(g_h1h[n1 * 32 + lane]);
                    float2 f2 = __half22float2(g_h1h[n2 * 32 + lane]);
                    float2 f3 = __half22float2(g_h1h[n3 * 32 + lane]);
                    a0 += f0.x; b0 += f0.y;
                    a1 += f1.x; b1 += f1.y;
                    a0 += f2.x; b0 += f2.y;
                    a1 += f3.x; b1 += f3.y;
                }
                for (; q < chunk; q++) {
                    int n0 = __shfl_sync(0xffffffffu, idx, q);
                    float2 f0 = __half22float2(g_h1h[n0 * 32 + lane]);
                    a0 += f0.x; b0 += f0.y;
                }
            }
            float inv = d > 0 ? 1.0f / (float)d : 0.0f;
            *(float2*)&sv[warp][g][2 * lane] =
                make_float2((a0 + a1) * inv, (b0 + b1) * inv);
            float2 root = __half22float2(g_h1h[n * 32 + lane]);
            *(float2*)&sv[warp][g][64 + 2 * lane] = root;
        }
        __syncwarp();
        float2 bias = *(float2*)&sb[2 * lane];
        float2 o[4];
#pragma unroll
        for (int g = 0; g < 4; g++) o[g] = bias;
#pragma unroll 4
        for (int k = 0; k < 128; k += 2) {
            float2 w0 = *(float2*)&sw[k * 64 + 2 * lane];
            float2 w1 = *(float2*)&sw[(k + 1) * 64 + 2 * lane];
#pragma unroll
            for (int g = 0; g < 4; g++) {
                float2 v = *(float2*)&sv[warp][g][k];
                o[g].x += v.x * w0.x + v.y * w1.x;
                o[g].y += v.x * w0.y + v.y * w1.y;
            }
        }
#pragma unroll
        for (int g = 0; g < 4; g++) {
            int n = nb + g;
            if (n >= N_NODES) break;
            float ss = o[g].x * o[g].x + o[g].y * o[g].y;
#pragma unroll
            for (int ofs = 16; ofs; ofs >>= 1) ss += __shfl_xor_sync(0xffffffffu, ss, ofs);
            float in2 = 1.0f / fmaxf(sqrtf(ss), 1e-12f);
            float2 r = make_float2(fmaxf(o[g].x * in2, 0.f), fmaxf(o[g].y * in2, 0.f));
            *(float2*)&g_h2[n * 64 + 2 * lane] = r;
        }
        __syncwarp();
    }
}

// ---------------- head: contiguous-range mean pool + MLP ----------------
__global__ void k_head(const float* __restrict__ p1w, const float* __restrict__ p1b,
                       const float* __restrict__ p2w, const float* __restrict__ p2b,
                       const float* __restrict__ ow,  const float* __restrict__ ob,
                       float* __restrict__ out) {
    __shared__ float part[4 * 64];
    __shared__ float sg[64], t1[64], t2[16];
    int g = blockIdx.x, t = threadIdx.x;
    int lo = g_lo[g], hi = g_lo[g + 1];
    int f = t & 63, r = t >> 6;
    float s = 0.f;
    for (int n = lo + r; n < hi; n += 4) s += g_h2[n * 64 + f];
    part[r * 64 + f] = s;
    __syncthreads();
    if (t < 64) {
        float tot = part[t] + part[64 + t] + part[128 + t] + part[192 + t];
        float cnt = (float)(hi - lo);
        sg[t] = tot / fmaxf(cnt, 1.0f);
    }
    __syncthreads();
    if (t < 64) {
        float s1 = p1b[t];
#pragma unroll 8
        for (int k = 0; k < 64; k++) s1 += sg[k] * p1w[k * 64 + t];
        t1[t] = fmaxf(s1, 0.f);
    }
    __syncthreads();
    if (t < 16) {
        float s2 = p2b[t];
#pragma unroll 8
        for (int k = 0; k < 64; k++) s2 += t1[k] * p2w[k * 16 + t];
        t2[t] = fmaxf(s2, 0.f);
    }
    __syncthreads();
    if (t == 0) {
        float o = ob[0];
#pragma unroll
        for (int k = 0; k < 16; k++) o += t2[k] * ow[k];
        out[g] = o;
    }
}

// ---------------- launch ----------------
extern "C" void kernel_launch(void* const* d_in, const int* in_sizes, int n_in,
                              void* d_out, int out_size) {
    const float* x     = (const float*)d_in[0];
    const int*   ei    = (const int*)d_in[1];
    const int*   batch = (const int*)d_in[2];
    int base = (n_in >= 18 && in_sizes[3] == 1) ? 4 : 3;
    const float* pre_w = (const float*)d_in[base + 0];
    const float* pre_b = (const float*)d_in[base + 1];
    const float* c1_wl = (const float*)d_in[base + 2];
    const float* c1_bl = (const float*)d_in[base + 3];
    const float* c1_wr = (const float*)d_in[base + 4];
    const float* c2_wl = (const float*)d_in[base + 5];
    const float* c2_bl = (const float*)d_in[base + 6];
    const float* c2_wr = (const float*)d_in[base + 7];
    const float* p1_w  = (const float*)d_in[base + 8];
    const float* p1_b  = (const float*)d_in[base + 9];
    const float* p2_w  = (const float*)d_in[base + 10];
    const float* p2_b  = (const float*)d_in[base + 11];
    const float* o_w   = (const float*)d_in[base + 12];
    const float* o_b   = (const float*)d_in[base + 13];

    const int* src = ei;
    const int* dst = ei + N_EDGES;
    float* out = (float*)d_out;

    const int T = 256;
    k_pre<<<(N_NODES + T - 1) / T, T>>>(x, pre_w, pre_b);        // also zeroes g_cnt
    k_hist<<<(N_EDGES / 4 + T - 1) / T, T>>>(dst);
    k_scan1<<<NB_SCAN, 256>>>();
    k_scan2<<<1, 128>>>();
    k_scan3<<<(N_NODES + T - 1) / T, T>>>(batch);
    k_fill<<<(N_EDGES / 4 + T - 1) / T, T>>>(src, dst);

    k_conv1<<<1184, 256>>>(c1_wl, c1_bl, c1_wr);
    k_conv2<<<592, 256>>>(c2_wl, c2_bl, c2_wr);

    k_head<<<N_GRAPHS, 256>>>(p1_w, p1_b, p2_w, p2_b, o_w, o_b, out);
    (void)out_size;
}

// round 10
// speedup vs baseline: 1.9096x; 1.0090x over previous
#include <cuda_runtime.h>
#include <cuda_fp16.h>
#include <cstdint>

#define N_NODES  100000
#define N_EDGES  1600000
#define N_GRAPHS 512
#define NB_SCAN  ((N_NODES + 1023) / 1024)   // 98
#define N_TILES  (N_NODES / 16)              // 6250 (exact)

// ---------------- device scratch (no allocations allowed) ----------------
__device__ __half2 g_h0h[N_NODES * 16];     // h0 fp16 pairs (64B/row)
__device__ __half2 g_h1h[N_NODES * 32];     // h1 fp16 pairs (128B/row)
__device__ __half2 g_h2h[N_NODES * 32];     // h2 fp16 pairs (128B/row)
__device__ int     g_cnt[N_NODES];
__device__ int     g_rs[N_NODES];
__device__ int     g_cur[N_NODES];
__device__ int     g_adj[N_EDGES];
__device__ int     g_bsum[NB_SCAN + 8];
__device__ int     g_lo[N_GRAPHS + 1];

// ---------------- mma helpers ----------------
__device__ __forceinline__ uint32_t smem_u32(const void* p) {
    return (uint32_t)__cvta_generic_to_shared(p);
}
__device__ __forceinline__ void ldsm_x4(uint32_t& a0, uint32_t& a1,
                                        uint32_t& a2, uint32_t& a3, uint32_t addr) {
    asm volatile("ldmatrix.sync.aligned.m8n8.x4.shared.b16 {%0,%1,%2,%3}, [%4];"
                 : "=r"(a0), "=r"(a1), "=r"(a2), "=r"(a3) : "r"(addr));
}
__device__ __forceinline__ void ldsm_x2t(uint32_t& b0, uint32_t& b1, uint32_t addr) {
    asm volatile("ldmatrix.sync.aligned.m8n8.x2.trans.shared.b16 {%0,%1}, [%2];"
                 : "=r"(b0), "=r"(b1) : "r"(addr));
}
__device__ __forceinline__ void mma16816(float c[4], uint32_t a0, uint32_t a1,
                                         uint32_t a2, uint32_t a3,
                                         uint32_t b0, uint32_t b1) {
    asm volatile("mma.sync.aligned.m16n8k16.row.col.f32.f16.f16.f32 "
                 "{%0,%1,%2,%3}, {%4,%5,%6,%7}, {%8,%9}, {%0,%1,%2,%3};"
                 : "+f"(c[0]), "+f"(c[1]), "+f"(c[2]), "+f"(c[3])
                 : "r"(a0), "r"(a1), "r"(a2), "r"(a3), "r"(b0), "r"(b1));
}

// ---------------- CSR build ----------------
__global__ void k_hist(const int* __restrict__ dst) {
    int i = blockIdx.x * blockDim.x + threadIdx.x;
    int e4 = i * 4;
    if (e4 + 3 < N_EDGES) {
        int4 d = *(const int4*)&dst[e4];
        atomicAdd(&g_cnt[d.x], 1);
        atomicAdd(&g_cnt[d.y], 1);
        atomicAdd(&g_cnt[d.z], 1);
        atomicAdd(&g_cnt[d.w], 1);
    } else if (e4 < N_EDGES) {
        for (int e = e4; e < N_EDGES; e++) atomicAdd(&g_cnt[dst[e]], 1);
    }
}

__global__ void k_scan1() {
    __shared__ int wsum[8];
    int b = blockIdx.x, t = threadIdx.x;
    int lane = t & 31, w = t >> 5;
    int base = b * 1024 + t * 4;
    int v[4];
#pragma unroll
    for (int q = 0; q < 4; q++) v[q] = (base + q < N_NODES) ? g_cnt[base + q] : 0;
    int tot = v[0] + v[1] + v[2] + v[3];
    int sc = tot;
#pragma unroll
    for (int o = 1; o < 32; o <<= 1) {
        int x = __shfl_up_sync(0xffffffffu, sc, o);
        if (lane >= o) sc += x;
    }
    if (lane == 31) wsum[w] = sc;
    __syncthreads();
    if (t == 0) {
        int r = 0;
#pragma unroll
        for (int i = 0; i < 8; i++) { int x = wsum[i]; wsum[i] = r; r += x; }
        g_bsum[b] = r;
    }
    __syncthreads();
    int run = wsum[w] + (sc - tot);
#pragma unroll
    for (int q = 0; q < 4; q++) {
        if (base + q < N_NODES) g_rs[base + q] = run;
        run += v[q];
    }
}

__global__ void k_scan2() {
    __shared__ int sb[NB_SCAN];
    int t = threadIdx.x;
    if (t < NB_SCAN) sb[t] = g_bsum[t];
    __syncthreads();
    if (t == 0) {
        int r = 0;
        for (int i = 0; i < NB_SCAN; i++) { int x = sb[i]; sb[i] = r; r += x; }
    }
    __syncthreads();
    if (t < NB_SCAN) g_bsum[t] = sb[t];
}

__global__ void k_scan3(const int* __restrict__ batch) {
    int i = blockIdx.x * blockDim.x + threadIdx.x;
    if (i >= N_NODES) return;
    int v = g_rs[i] + g_bsum[i >> 10];
    g_rs[i] = v;
    g_cur[i] = v;
    int b = batch[i];
    int bn = (i + 1 < N_NODES) ? batch[i + 1] : N_GRAPHS;
    if (i == 0)
        for (int g = 0; g <= b; g++) g_lo[g] = 0;
    for (int g = b + 1; g <= bn; g++) g_lo[g] = i + 1;
}

__global__ void k_fill(const int* __restrict__ src, const int* __restrict__ dst) {
    int i = blockIdx.x * blockDim.x + threadIdx.x;
    int e4 = i * 4;
    if (e4 + 3 < N_EDGES) {
        int4 s = *(const int4*)&src[e4];
        int4 d = *(const int4*)&dst[e4];
        g_adj[atomicAdd(&g_cur[d.x], 1)] = s.x;
        g_adj[atomicAdd(&g_cur[d.y], 1)] = s.y;
        g_adj[atomicAdd(&g_cur[d.z], 1)] = s.z;
        g_adj[atomicAdd(&g_cur[d.w], 1)] = s.w;
    } else if (e4 < N_EDGES) {
        for (int e = e4; e < N_EDGES; e++)
            g_adj[atomicAdd(&g_cur[dst[e]], 1)] = src[e];
    }
}

// ---------------- pre: h0 = relu(x @ pre_w + pre_b) -> fp16; zero cnt ----
__global__ void k_pre(const float* __restrict__ x,
                      const float* __restrict__ w,
                      const float* __restrict__ b) {
    __shared__ float sw[5 * 32];
    __shared__ float sb[32];
    int t = threadIdx.x;
    if (t < 160) sw[t] = w[t];
    if (t < 32)  sb[t] = b[t];
    __syncthreads();
    int n = blockIdx.x * blockDim.x + t;
    if (n >= N_NODES) return;
    g_cnt[n] = 0;
    float xi[5];
#pragma unroll
    for (int i = 0; i < 5; i++) xi[i] = x[n * 5 + i];
    __half2 hv[16];
#pragma unroll
    for (int j2 = 0; j2 < 16; j2++) {
        float o0 = sb[2 * j2], o1 = sb[2 * j2 + 1];
#pragma unroll
        for (int i = 0; i < 5; i++) {
            o0 += xi[i] * sw[i * 32 + 2 * j2];
            o1 += xi[i] * sw[i * 32 + 2 * j2 + 1];
        }
        hv[j2] = __floats2half2_rn(fmaxf(o0, 0.f), fmaxf(o1, 0.f));
    }
    uint4* dstp = (uint4*)&g_h0h[n * 16];
    dstp[0] = ((uint4*)hv)[0];
    dstp[1] = ((uint4*)hv)[1];
    dstp[2] = ((uint4*)hv)[2];
    dstp[3] = ((uint4*)hv)[3];
}

// ---------------- conv1: gather fp16 h0 + tensor-core combine ------------
// A row (per node, 72 halves padded): v = [agg(0:32) | h(32:64)]
// B (64x72 halves padded): k<32 -> Wl[k], else Wr[k-32]
__global__ void __launch_bounds__(256) k_conv1(const float* __restrict__ wl,
                                               const float* __restrict__ bl,
                                               const float* __restrict__ wr) {
    extern __shared__ char dyn[];
    half*  sB    = (half*)dyn;                                  // 64*72
    half*  sA    = (half*)(dyn + 64 * 72 * 2);                  // 8*16*72
    float* sbias = (float*)(dyn + 64 * 72 * 2 + 8 * 16 * 72 * 2);
    int t = threadIdx.x;
    for (int i = t; i < 64 * 64; i += 256) {
        int k = i >> 6, n = i & 63;
        float v = (k < 32) ? wl[k * 64 + n] : wr[(k - 32) * 64 + n];
        sB[k * 72 + n] = __float2half(v);
    }
    if (t < 64) sbias[t] = bl[t];
    __syncthreads();

    int lane = t & 31, warp = t >> 5;
    int tile = blockIdx.x * 8 + warp;
    if (tile >= N_TILES) return;
    int base = tile * 16;
    half2* sa2 = (half2*)(sA + warp * 16 * 72);   // row stride 36 half2
    int l15 = lane & 15;
    bool hihalf = lane >= 16;

    for (int r = 0; r < 16; r++) {
        int n = base + r;
        int rs = g_rs[n], d = g_cnt[n];
        float2 acc0 = make_float2(0.f, 0.f), acc1 = make_float2(0.f, 0.f);
        for (int j = 0; j < d; j += 32) {
            int chunk = min(32, d - j);
            int idx = (lane < chunk) ? g_adj[rs + j + lane] : 0;
            int q = 0;
            for (; q + 3 < chunk; q += 4) {
                int nA = __shfl_sync(0xffffffffu, idx, q);
                int nB = __shfl_sync(0xffffffffu, idx, q + 1);
                int nC = __shfl_sync(0xffffffffu, idx, q + 2);
                int nD = __shfl_sync(0xffffffffu, idx, q + 3);
                int s0 = hihalf ? nB : nA;
                int s1 = hihalf ? nD : nC;
                float2 f0 = __half22float2(g_h0h[s0 * 16 + l15]);
                float2 f1 = __half22float2(g_h0h[s1 * 16 + l15]);
                acc0.x += f0.x; acc0.y += f0.y;
                acc1.x += f1.x; acc1.y += f1.y;
            }
            for (; q + 1 < chunk; q += 2) {
                int nA = __shfl_sync(0xffffffffu, idx, q);
                int nB = __shfl_sync(0xffffffffu, idx, q + 1);
                int s0 = hihalf ? nB : nA;
                float2 f0 = __half22float2(g_h0h[s0 * 16 + l15]);
                acc0.x += f0.x; acc0.y += f0.y;
            }
            if (q < chunk) {
                int nA = __shfl_sync(0xffffffffu, idx, q);
                if (!hihalf) {
                    float2 f0 = __half22float2(g_h0h[nA * 16 + l15]);
                    acc0.x += f0.x; acc0.y += f0.y;
                }
            }
        }
        acc0.x += acc1.x; acc0.y += acc1.y;
        acc0.x += __shfl_xor_sync(0xffffffffu, acc0.x, 16);
        acc0.y += __shfl_xor_sync(0xffffffffu, acc0.y, 16);
        float inv = d > 0 ? 1.0f / (float)d : 0.0f;
        if (!hihalf) {
            sa2[r * 36 + l15]      = __floats2half2_rn(acc0.x * inv, acc0.y * inv);
            sa2[r * 36 + 16 + l15] = g_h0h[n * 16 + l15];
        }
    }
    __syncwarp();

    // GEMM: [16 x 64] @ [64 x 64], fp32 accum
    uint32_t aBase = smem_u32(sA + warp * 16 * 72) + (uint32_t)((lane & 15) * 144 + (lane >> 4) * 16);
    uint32_t bBase = smem_u32(sB) + (uint32_t)((lane & 15) * 144);
    float c[8][4];
#pragma unroll
    for (int nt = 0; nt < 8; nt++) { c[nt][0] = c[nt][1] = c[nt][2] = c[nt][3] = 0.f; }
#pragma unroll
    for (int kk = 0; kk < 4; kk++) {
        uint32_t a0, a1, a2, a3;
        ldsm_x4(a0, a1, a2, a3, aBase + kk * 32);
#pragma unroll
        for (int nt = 0; nt < 8; nt++) {
            uint32_t b0, b1;
            ldsm_x2t(b0, b1, bBase + (uint32_t)(kk * 16 * 144 + nt * 16));
            mma16816(c[nt], a0, a1, a2, a3, b0, b1);
        }
    }
    // epilogue: bias + row L2 norm + relu -> fp16
    int q = lane & 3, rlo = lane >> 2;
    float ssl = 0.f, ssh = 0.f;
#pragma unroll
    for (int nt = 0; nt < 8; nt++) {
        float b0 = sbias[nt * 8 + q * 2], b1 = sbias[nt * 8 + q * 2 + 1];
        c[nt][0] += b0; c[nt][1] += b1; c[nt][2] += b0; c[nt][3] += b1;
        ssl += c[nt][0] * c[nt][0] + c[nt][1] * c[nt][1];
        ssh += c[nt][2] * c[nt][2] + c[nt][3] * c[nt][3];
    }
    ssl += __shfl_xor_sync(0xffffffffu, ssl, 1);
    ssl += __shfl_xor_sync(0xffffffffu, ssl, 2);
    ssh += __shfl_xor_sync(0xffffffffu, ssh, 1);
    ssh += __shfl_xor_sync(0xffffffffu, ssh, 2);
    float il = 1.0f / fmaxf(sqrtf(ssl), 1e-12f);
    float ih = 1.0f / fmaxf(sqrtf(ssh), 1e-12f);
    int nlo = base + rlo, nhi = nlo + 8;
#pragma unroll
    for (int nt = 0; nt < 8; nt++) {
        g_h1h[nlo * 32 + nt * 4 + q] =
            __floats2half2_rn(fmaxf(c[nt][0] * il, 0.f), fmaxf(c[nt][1] * il, 0.f));
        g_h1h[nhi * 32 + nt * 4 + q] =
            __floats2half2_rn(fmaxf(c[nt][2] * ih, 0.f), fmaxf(c[nt][3] * ih, 0.f));
    }
}

// ---------------- conv2: gather fp16 h1 + tensor-core combine ------------
// A row (136 halves padded): v = [agg(0:64) | h(64:128)]
// B (128x72 halves padded): k<64 -> Wl[k], else Wr[k-64]
__global__ void __launch_bounds__(256) k_conv2(const float* __restrict__ wl,
                                               const float* __restrict__ bl,
                                               const float* __restrict__ wr) {
    extern __shared__ char dyn[];
    half*  sB    = (half*)dyn;                                   // 128*72
    half*  sA    = (half*)(dyn + 128 * 72 * 2);                  // 8*16*136
    float* sbias = (float*)(dyn + 128 * 72 * 2 + 8 * 16 * 136 * 2);
    int t = threadIdx.x;
    for (int i = t; i < 128 * 64; i += 256) {
        int k = i >> 6, n = i & 63;
        float v = (k < 64) ? wl[k * 64 + n] : wr[(k - 64) * 64 + n];
        sB[k * 72 + n] = __float2half(v);
    }
    if (t < 64) sbias[t] = bl[t];
    __syncthreads();

    int lane = t & 31, warp = t >> 5;
    int tile = blockIdx.x * 8 + warp;
    if (tile >= N_TILES) return;
    int base = tile * 16;
    half2* sa2 = (half2*)(sA + warp * 16 * 136);   // row stride 68 half2

    for (int r = 0; r < 16; r++) {
        int n = base + r;
        int rs = g_rs[n], d = g_cnt[n];
        float a0 = 0.f, b0 = 0.f, a1 = 0.f, b1 = 0.f;
        for (int j = 0; j < d; j += 32) {
            int chunk = min(32, d - j);
            int idx = (lane < chunk) ? g_adj[rs + j + lane] : 0;
            int q = 0;
            for (; q + 3 < chunk; q += 4) {
                int n0 = __shfl_sync(0xffffffffu, idx, q);
                int n1 = __shfl_sync(0xffffffffu, idx, q + 1);
                int n2 = __shfl_sync(0xffffffffu, idx, q + 2);
                int n3 = __shfl_sync(0xffffffffu, idx, q + 3);
                float2 f0 = __half22float2(g_h1h[n0 * 32 + lane]);
                float2 f1 = __half22float2(g_h1h[n1 * 32 + lane]);
                float2 f2 = __half22float2(g_h1h[n2 * 32 + lane]);
                float2 f3 = __half22float2(g_h1h[n3 * 32 + lane]);
                a0 += f0.x; b0 += f0.y;
                a1 += f1.x; b1 += f1.y;
                a0 += f2.x; b0 += f2.y;
                a1 += f3.x; b1 += f3.y;
            }
            for (; q < chunk; q++) {
                int n0 = __shfl_sync(0xffffffffu, idx, q);
                float2 f0 = __half22float2(g_h1h[n0 * 32 + lane]);
                a0 += f0.x; b0 += f0.y;
            }
        }
        float inv = d > 0 ? 1.0f / (float)d : 0.0f;
        sa2[r * 68 + lane]      = __floats2half2_rn((a0 + a1) * inv, (b0 + b1) * inv);
        sa2[r * 68 + 32 + lane] = g_h1h[n * 32 + lane];
    }
    __syncwarp();

    // GEMM: [16 x 128] @ [128 x 64], fp32 accum
    uint32_t aBase = smem_u32(sA + warp * 16 * 136) + (uint32_t)((lane & 15) * 272 + (lane >> 4) * 16);
    uint32_t bBase = smem_u32(sB) + (uint32_t)((lane & 15) * 144);
    float c[8][4];
#pragma unroll
    for (int nt = 0; nt < 8; nt++) { c[nt][0] = c[nt][1] = c[nt][2] = c[nt][3] = 0.f; }
#pragma unroll
    for (int kk = 0; kk < 8; kk++) {
        uint32_t a0, a1, a2, a3;
        ldsm_x4(a0, a1, a2, a3, aBase + kk * 32);
#pragma unroll
        for (int nt = 0; nt < 8; nt++) {
            uint32_t b0, b1;
            ldsm_x2t(b0, b1, bBase + (uint32_t)(kk * 16 * 144 + nt * 16));
            mma16816(c[nt], a0, a1, a2, a3, b0, b1);
        }
    }
    int q = lane & 3, rlo = lane >> 2;
    float ssl = 0.f, ssh = 0.f;
#pragma unroll
    for (int nt = 0; nt < 8; nt++) {
        float bb0 = sbias[nt * 8 + q * 2], bb1 = sbias[nt * 8 + q * 2 + 1];
        c[nt][0] += bb0; c[nt][1] += bb1; c[nt][2] += bb0; c[nt][3] += bb1;
        ssl += c[nt][0] * c[nt][0] + c[nt][1] * c[nt][1];
        ssh += c[nt][2] * c[nt][2] + c[nt][3] * c[nt][3];
    }
    ssl += __shfl_xor_sync(0xffffffffu, ssl, 1);
    ssl += __shfl_xor_sync(0xffffffffu, ssl, 2);
    ssh += __shfl_xor_sync(0xffffffffu, ssh, 1);
    ssh += __shfl_xor_sync(0xffffffffu, ssh, 2);
    float il = 1.0f / fmaxf(sqrtf(ssl), 1e-12f);
    float ih = 1.0f / fmaxf(sqrtf(ssh), 1e-12f);
    int nlo = base + rlo, nhi = nlo + 8;
#pragma unroll
    for (int nt = 0; nt < 8; nt++) {
        g_h2h[nlo * 32 + nt * 4 + q] =
            __floats2half2_rn(fmaxf(c[nt][0] * il, 0.f), fmaxf(c[nt][1] * il, 0.f));
        g_h2h[nhi * 32 + nt * 4 + q] =
            __floats2half2_rn(fmaxf(c[nt][2] * ih, 0.f), fmaxf(c[nt][3] * ih, 0.f));
    }
}

// ---------------- head: contiguous-range mean pool + MLP ----------------
__global__ void k_head(const float* __restrict__ p1w, const float* __restrict__ p1b,
                       const float* __restrict__ p2w, const float* __restrict__ p2b,
                       const float* __restrict__ ow,  const float* __restrict__ ob,
                       float* __restrict__ out) {
    __shared__ float part[4 * 64];
    __shared__ float sg[64], t1[64], t2[16];
    int g = blockIdx.x, t = threadIdx.x;
    int lo = g_lo[g], hi = g_lo[g + 1];
    int f = t & 63, r = t >> 6;
    float s = 0.f;
    for (int n = lo + r; n < hi; n += 4) {
        __half2 v = g_h2h[n * 32 + (f >> 1)];
        s += (f & 1) ? __half2float(__high2half(v)) : __half2float(__low2half(v));
    }
    part[r * 64 + f] = s;
    __syncthreads();
    if (t < 64) {
        float tot = part[t] + part[64 + t] + part[128 + t] + part[192 + t];
        float cnt = (float)(hi - lo);
        sg[t] = tot / fmaxf(cnt, 1.0f);
    }
    __syncthreads();
    if (t < 64) {
        float s1 = p1b[t];
#pragma unroll 8
        for (int k = 0; k < 64; k++) s1 += sg[k] * p1w[k * 64 + t];
        t1[t] = fmaxf(s1, 0.f);
    }
    __syncthreads();
    if (t < 16) {
        float s2 = p2b[t];
#pragma unroll 8
        for (int k = 0; k < 64; k++) s2 += t1[k] * p2w[k * 16 + t];
        t2[t] = fmaxf(s2, 0.f);
    }
    __syncthreads();
    if (t == 0) {
        float o = ob[0];
#pragma unroll
        for (int k = 0; k < 16; k++) o += t2[k] * ow[k];
        out[g] = o;
    }
}

// ---------------- launch ----------------
extern "C" void kernel_launch(void* const* d_in, const int* in_sizes, int n_in,
                              void* d_out, int out_size) {
    const float* x     = (const float*)d_in[0];
    const int*   ei    = (const int*)d_in[1];
    const int*   batch = (const int*)d_in[2];
    int base = (n_in >= 18 && in_sizes[3] == 1) ? 4 : 3;
    const float* pre_w = (const float*)d_in[base + 0];
    const float* pre_b = (const float*)d_in[base + 1];
    const float* c1_wl = (const float*)d_in[base + 2];
    const float* c1_bl = (const float*)d_in[base + 3];
    const float* c1_wr = (const float*)d_in[base + 4];
    const float* c2_wl = (const float*)d_in[base + 5];
    const float* c2_bl = (const float*)d_in[base + 6];
    const float* c2_wr = (const float*)d_in[base + 7];
    const float* p1_w  = (const float*)d_in[base + 8];
    const float* p1_b  = (const float*)d_in[base + 9];
    const float* p2_w  = (const float*)d_in[base + 10];
    const float* p2_b  = (const float*)d_in[base + 11];
    const float* o_w   = (const float*)d_in[base + 12];
    const float* o_b   = (const float*)d_in[base + 13];

    const int* src = ei;
    const int* dst = ei + N_EDGES;
    float* out = (float*)d_out;

    const size_t smem1 = 64 * 72 * 2 + 8 * 16 * 72 * 2 + 256;     // 27904
    const size_t smem2 = 128 * 72 * 2 + 8 * 16 * 136 * 2 + 256;   // 53504
    cudaFuncSetAttribute(k_conv1, cudaFuncAttributeMaxDynamicSharedMemorySize, (int)smem1);
    cudaFuncSetAttribute(k_conv2, cudaFuncAttributeMaxDynamicSharedMemorySize, (int)smem2);

    const int T = 256;
    k_pre<<<(N_NODES + T - 1) / T, T>>>(x, pre_w, pre_b);        // also zeroes g_cnt
    k_hist<<<(N_EDGES / 4 + T - 1) / T, T>>>(dst);
    k_scan1<<<NB_SCAN, 256>>>();
    k_scan2<<<1, 128>>>();
    k_scan3<<<(N_NODES + T - 1) / T, T>>>(batch);
    k_fill<<<(N_EDGES / 4 + T - 1) / T, T>>>(src, dst);

    int nblk = (N_TILES + 7) / 8;   // 782
    k_conv1<<<nblk, 256, smem1>>>(c1_wl, c1_bl, c1_wr);
    k_conv2<<<nblk, 256, smem2>>>(c2_wl, c2_bl, c2_wr);

    k_head<<<N_GRAPHS, 256>>>(p1_w, p1_b, p2_w, p2_b, o_w, o_b, out);
    (void)out_size;
}

// round 13
// speedup vs baseline: 2.1581x; 1.1301x over previous
#include <cuda_runtime.h>
#include <cuda_fp16.h>
#include <cstdint>

#define N_NODES  100000
#define N_EDGES  1600000
#define N_GRAPHS 512
#define NB_SCAN  ((N_NODES + 1023) / 1024)   // 98
#define N_TILES  (N_NODES / 16)              // 6250 (exact)
#define PRE_BLKS ((N_NODES + 255) / 256)     // 391
#define HIST_BLKS ((N_EDGES / 4 + 255) / 256) // 1563

// ---------------- device scratch (no allocations allowed) ----------------
// NOTE: g_cnt is zero-initialized at load and re-zeroed at the END of each
// kernel_launch (in k_head), so k_prehist can run pre+hist concurrently.
__device__ __half2 g_h0h[N_NODES * 16];     // h0 fp16 pairs (64B/row)
__device__ __half2 g_h1h[N_NODES * 32];     // h1 fp16 pairs (128B/row)
__device__ __half2 g_h2h[N_NODES * 32];     // h2 fp16 pairs (128B/row)
__device__ int     g_cnt[N_NODES];
__device__ int     g_rs[N_NODES];
__device__ int     g_cur[N_NODES];
__device__ int     g_adj[N_EDGES];
__device__ int     g_bsum[NB_SCAN + 8];
__device__ int     g_lo[N_GRAPHS + 1];

// ---------------- mma helpers ----------------
__device__ __forceinline__ uint32_t smem_u32(const void* p) {
    return (uint32_t)__cvta_generic_to_shared(p);
}
__device__ __forceinline__ void ldsm_x4(uint32_t& a0, uint32_t& a1,
                                        uint32_t& a2, uint32_t& a3, uint32_t addr) {
    asm volatile("ldmatrix.sync.aligned.m8n8.x4.shared.b16 {%0,%1,%2,%3}, [%4];"
                 : "=r"(a0), "=r"(a1), "=r"(a2), "=r"(a3) : "r"(addr));
}
__device__ __forceinline__ void ldsm_x2t(uint32_t& b0, uint32_t& b1, uint32_t addr) {
    asm volatile("ldmatrix.sync.aligned.m8n8.x2.trans.shared.b16 {%0,%1}, [%2];"
                 : "=r"(b0), "=r"(b1) : "r"(addr));
}
__device__ __forceinline__ void mma16816(float c[4], uint32_t a0, uint32_t a1,
                                         uint32_t a2, uint32_t a3,
                                         uint32_t b0, uint32_t b1) {
    asm volatile("mma.sync.aligned.m16n8k16.row.col.f32.f16.f16.f32 "
                 "{%0,%1,%2,%3}, {%4,%5,%6,%7}, {%8,%9}, {%0,%1,%2,%3};"
                 : "+f"(c[0]), "+f"(c[1]), "+f"(c[2]), "+f"(c[3])
                 : "r"(a0), "r"(a1), "r"(a2), "r"(a3), "r"(b0), "r"(b1));
}

// ---------------- fused pre (blocks 0..390) + hist (rest) ----------------
// g_cnt is already zero on entry (zeroed by k_head at end of previous call,
// or by static zero-init on the very first call), so hist can run
// concurrently with pre.
__global__ void k_prehist(const float* __restrict__ x,
                          const float* __restrict__ w,
                          const float* __restrict__ b,
                          const int* __restrict__ dst) {
    int t = threadIdx.x;
    if (blockIdx.x < PRE_BLKS) {
        __shared__ float sw[5 * 32];
        __shared__ float sb[32];
        if (t < 160) sw[t] = w[t];
        if (t < 32)  sb[t] = b[t];
        __syncthreads();
        int n = blockIdx.x * 256 + t;
        if (n >= N_NODES) return;
        float xi[5];
#pragma unroll
        for (int i = 0; i < 5; i++) xi[i] = x[n * 5 + i];
        __half2 hv[16];
#pragma unroll
        for (int j2 = 0; j2 < 16; j2++) {
            float o0 = sb[2 * j2], o1 = sb[2 * j2 + 1];
#pragma unroll
            for (int i = 0; i < 5; i++) {
                o0 += xi[i] * sw[i * 32 + 2 * j2];
                o1 += xi[i] * sw[i * 32 + 2 * j2 + 1];
            }
            hv[j2] = __floats2half2_rn(fmaxf(o0, 0.f), fmaxf(o1, 0.f));
        }
        uint4* dstp = (uint4*)&g_h0h[n * 16];
        dstp[0] = ((uint4*)hv)[0];
        dstp[1] = ((uint4*)hv)[1];
        dstp[2] = ((uint4*)hv)[2];
        dstp[3] = ((uint4*)hv)[3];
    } else {
        int i = (blockIdx.x - PRE_BLKS) * 256 + t;
        int e4 = i * 4;
        if (e4 + 3 < N_EDGES) {
            int4 d = *(const int4*)&dst[e4];
            atomicAdd(&g_cnt[d.x], 1);
            atomicAdd(&g_cnt[d.y], 1);
            atomicAdd(&g_cnt[d.z], 1);
            atomicAdd(&g_cnt[d.w], 1);
        } else if (e4 < N_EDGES) {
            for (int e = e4; e < N_EDGES; e++) atomicAdd(&g_cnt[dst[e]], 1);
        }
    }
}

__global__ void k_scan1() {
    __shared__ int wsum[8];
    int b = blockIdx.x, t = threadIdx.x;
    int lane = t & 31, w = t >> 5;
    int base = b * 1024 + t * 4;
    int v[4];
#pragma unroll
    for (int q = 0; q < 4; q++) v[q] = (base + q < N_NODES) ? g_cnt[base + q] : 0;
    int tot = v[0] + v[1] + v[2] + v[3];
    int sc = tot;
#pragma unroll
    for (int o = 1; o < 32; o <<= 1) {
        int x = __shfl_up_sync(0xffffffffu, sc, o);
        if (lane >= o) sc += x;
    }
    if (lane == 31) wsum[w] = sc;
    __syncthreads();
    if (t == 0) {
        int r = 0;
#pragma unroll
        for (int i = 0; i < 8; i++) { int x = wsum[i]; wsum[i] = r; r += x; }
        g_bsum[b] = r;
    }
    __syncthreads();
    int run = wsum[w] + (sc - tot);
#pragma unroll
    for (int q = 0; q < 4; q++) {
        if (base + q < N_NODES) g_rs[base + q] = run;
        run += v[q];
    }
}

// scan3 with embedded scan2 (each block redundantly scans the 98 sums) + bounds
__global__ void k_scan23(const int* __restrict__ batch) {
    __shared__ int psum[NB_SCAN];
    int t = threadIdx.x;
    if (t < NB_SCAN) psum[t] = g_bsum[t];
    __syncthreads();
    if (t == 0) {
        int r = 0;
#pragma unroll 7
        for (int i = 0; i < NB_SCAN; i++) { int x = psum[i]; psum[i] = r; r += x; }
    }
    __syncthreads();
    int i = blockIdx.x * 256 + t;
    if (i >= N_NODES) return;
    int v = g_rs[i] + psum[i >> 10];
    g_rs[i] = v;
    g_cur[i] = v;
    int b = batch[i];
    int bn = (i + 1 < N_NODES) ? batch[i + 1] : N_GRAPHS;
    if (i == 0)
        for (int g = 0; g <= b; g++) g_lo[g] = 0;
    for (int g = b + 1; g <= bn; g++) g_lo[g] = i + 1;
}

__global__ void k_fill(const int* __restrict__ src, const int* __restrict__ dst) {
    int i = blockIdx.x * blockDim.x + threadIdx.x;
    int e4 = i * 4;
    if (e4 + 3 < N_EDGES) {
        int4 s = *(const int4*)&src[e4];
        int4 d = *(const int4*)&dst[e4];
        g_adj[atomicAdd(&g_cur[d.x], 1)] = s.x;
        g_adj[atomicAdd(&g_cur[d.y], 1)] = s.y;
        g_adj[atomicAdd(&g_cur[d.z], 1)] = s.z;
        g_adj[atomicAdd(&g_cur[d.w], 1)] = s.w;
    } else if (e4 < N_EDGES) {
        for (int e = e4; e < N_EDGES; e++)
            g_adj[atomicAdd(&g_cur[dst[e]], 1)] = src[e];
    }
}

// ---------------- conv1: deep-MLP gather + tensor-core combine -----------
__global__ void __launch_bounds__(256) k_conv1(const float* __restrict__ wl,
                                               const float* __restrict__ bl,
                                               const float* __restrict__ wr) {
    extern __shared__ char dyn[];
    half*  sB    = (half*)dyn;                                  // 64*72
    half*  sA    = (half*)(dyn + 64 * 72 * 2);                  // 8*16*72
    float* sbias = (float*)(dyn + 64 * 72 * 2 + 8 * 16 * 72 * 2);
    int t = threadIdx.x;
    for (int i = t; i < 64 * 64; i += 256) {
        int k = i >> 6, n = i & 63;
        float v = (k < 32) ? wl[k * 64 + n] : wr[(k - 32) * 64 + n];
        sB[k * 72 + n] = __float2half(v);
    }
    if (t < 64) sbias[t] = bl[t];
    __syncthreads();

    int lane = t & 31, warp = t >> 5;
    int tile = blockIdx.x * 8 + warp;
    if (tile >= N_TILES) return;
    int base = tile * 16;
    half2* sa2 = (half2*)(sA + warp * 16 * 72);   // row stride 36 half2
    int l15 = lane & 15;
    bool hihalf = lane >= 16;

    for (int r = 0; r < 16; r++) {
        int n = base + r;
        int rs = g_rs[n], d = g_cnt[n];
        float2 ac0 = make_float2(0.f, 0.f), ac1 = make_float2(0.f, 0.f);
        float2 ac2 = make_float2(0.f, 0.f), ac3 = make_float2(0.f, 0.f);
        for (int j = 0; j < d; j += 32) {
            int chunk = min(32, d - j);
            int idx = (lane < chunk) ? g_adj[rs + j + lane] : 0;
            int q = 0;
            for (; q + 7 < chunk; q += 8) {
                int nA = __shfl_sync(0xffffffffu, idx, q);
                int nB = __shfl_sync(0xffffffffu, idx, q + 1);
                int nC = __shfl_sync(0xffffffffu, idx, q + 2);
                int nD = __shfl_sync(0xffffffffu, idx, q + 3);
                int nE = __shfl_sync(0xffffffffu, idx, q + 4);
                int nF = __shfl_sync(0xffffffffu, idx, q + 5);
                int nG = __shfl_sync(0xffffffffu, idx, q + 6);
                int nH = __shfl_sync(0xffffffffu, idx, q + 7);
                int s0 = hihalf ? nB : nA;
                int s1 = hihalf ? nD : nC;
                int s2 = hihalf ? nF : nE;
                int s3 = hihalf ? nH : nG;
                float2 f0 = __half22float2(g_h0h[s0 * 16 + l15]);
                float2 f1 = __half22float2(g_h0h[s1 * 16 + l15]);
                float2 f2 = __half22float2(g_h0h[s2 * 16 + l15]);
                float2 f3 = __half22float2(g_h0h[s3 * 16 + l15]);
                ac0.x += f0.x; ac0.y += f0.y;
                ac1.x += f1.x; ac1.y += f1.y;
                ac2.x += f2.x; ac2.y += f2.y;
                ac3.x += f3.x; ac3.y += f3.y;
            }
            for (; q + 3 < chunk; q += 4) {
                int nA = __shfl_sync(0xffffffffu, idx, q);
                int nB = __shfl_sync(0xffffffffu, idx, q + 1);
                int nC = __shfl_sync(0xffffffffu, idx, q + 2);
                int nD = __shfl_sync(0xffffffffu, idx, q + 3);
                int s0 = hihalf ? nB : nA;
                int s1 = hihalf ? nD : nC;
                float2 f0 = __half22float2(g_h0h[s0 * 16 + l15]);
                float2 f1 = __half22float2(g_h0h[s1 * 16 + l15]);
                ac0.x += f0.x; ac0.y += f0.y;
                ac1.x += f1.x; ac1.y += f1.y;
            }
            for (; q + 1 < chunk; q += 2) {
                int nA = __shfl_sync(0xffffffffu, idx, q);
                int nB = __shfl_sync(0xffffffffu, idx, q + 1);
                int s0 = hihalf ? nB : nA;
                float2 f0 = __half22float2(g_h0h[s0 * 16 + l15]);
                ac0.x += f0.x; ac0.y += f0.y;
            }
            if (q < chunk) {
                int nA = __shfl_sync(0xffffffffu, idx, q);
                if (!hihalf) {
                    float2 f0 = __half22float2(g_h0h[nA * 16 + l15]);
                    ac0.x += f0.x; ac0.y += f0.y;
                }
            }
        }
        ac0.x += ac1.x + ac2.x + ac3.x;
        ac0.y += ac1.y + ac2.y + ac3.y;
        ac0.x += __shfl_xor_sync(0xffffffffu, ac0.x, 16);
        ac0.y += __shfl_xor_sync(0xffffffffu, ac0.y, 16);
        float inv = d > 0 ? 1.0f / (float)d : 0.0f;
        if (!hihalf) {
            sa2[r * 36 + l15]      = __floats2half2_rn(ac0.x * inv, ac0.y * inv);
            sa2[r * 36 + 16 + l15] = g_h0h[n * 16 + l15];
        }
    }
    __syncwarp();

    // GEMM: [16 x 64] @ [64 x 64], fp32 accum
    uint32_t aBase = smem_u32(sA + warp * 16 * 72) + (uint32_t)((lane & 15) * 144 + (lane >> 4) * 16);
    uint32_t bBase = smem_u32(sB) + (uint32_t)((lane & 15) * 144);
    float c[8][4];
#pragma unroll
    for (int nt = 0; nt < 8; nt++) { c[nt][0] = c[nt][1] = c[nt][2] = c[nt][3] = 0.f; }
#pragma unroll
    for (int kk = 0; kk < 4; kk++) {
        uint32_t a0, a1, a2, a3;
        ldsm_x4(a0, a1, a2, a3, aBase + kk * 32);
#pragma unroll
        for (int nt = 0; nt < 8; nt++) {
            uint32_t b0, b1;
            ldsm_x2t(b0, b1, bBase + (uint32_t)(kk * 16 * 144 + nt * 16));
            mma16816(c[nt], a0, a1, a2, a3, b0, b1);
        }
    }
    int q = lane & 3, rlo = lane >> 2;
    float ssl = 0.f, ssh = 0.f;
#pragma unroll
    for (int nt = 0; nt < 8; nt++) {
        float b0 = sbias[nt * 8 + q * 2], b1 = sbias[nt * 8 + q * 2 + 1];
        c[nt][0] += b0; c[nt][1] += b1; c[nt][2] += b0; c[nt][3] += b1;
        ssl += c[nt][0] * c[nt][0] + c[nt][1] * c[nt][1];
        ssh += c[nt][2] * c[nt][2] + c[nt][3] * c[nt][3];
    }
    ssl += __shfl_xor_sync(0xffffffffu, ssl, 1);
    ssl += __shfl_xor_sync(0xffffffffu, ssl, 2);
    ssh += __shfl_xor_sync(0xffffffffu, ssh, 1);
    ssh += __shfl_xor_sync(0xffffffffu, ssh, 2);
    float il = 1.0f / fmaxf(sqrtf(ssl), 1e-12f);
    float ih = 1.0f / fmaxf(sqrtf(ssh), 1e-12f);
    int nlo = base + rlo, nhi = nlo + 8;
#pragma unroll
    for (int nt = 0; nt < 8; nt++) {
        g_h1h[nlo * 32 + nt * 4 + q] =
            __floats2half2_rn(fmaxf(c[nt][0] * il, 0.f), fmaxf(c[nt][1] * il, 0.f));
        g_h1h[nhi * 32 + nt * 4 + q] =
            __floats2half2_rn(fmaxf(c[nt][2] * ih, 0.f), fmaxf(c[nt][3] * ih, 0.f));
    }
}

// ---------------- conv2: deep-MLP gather + tensor-core combine -----------
__global__ void __launch_bounds__(256) k_conv2(const float* __restrict__ wl,
                                               const float* __restrict__ bl,
                                               const float* __restrict__ wr) {
    extern __shared__ char dyn[];
    half*  sB    = (half*)dyn;                                   // 128*72
    half*  sA    = (half*)(dyn + 128 * 72 * 2);                  // 8*16*136
    float* sbias = (float*)(dyn + 128 * 72 * 2 + 8 * 16 * 136 * 2);
    int t = threadIdx.x;
    for (int i = t; i < 128 * 64; i += 256) {
        int k = i >> 6, n = i & 63;
        float v = (k < 64) ? wl[k * 64 + n] : wr[(k - 64) * 64 + n];
        sB[k * 72 + n] = __float2half(v);
    }
    if (t < 64) sbias[t] = bl[t];
    __syncthreads();

    int lane = t & 31, warp = t >> 5;
    int tile = blockIdx.x * 8 + warp;
    if (tile >= N_TILES) return;
    int base = tile * 16;
    half2* sa2 = (half2*)(sA + warp * 16 * 136);   // row stride 68 half2

    for (int r = 0; r < 16; r++) {
        int n = base + r;
        int rs = g_rs[n], d = g_cnt[n];
        float a0 = 0.f, b0 = 0.f, a1 = 0.f, b1 = 0.f;
        float a2 = 0.f, b2 = 0.f, a3 = 0.f, b3 = 0.f;
        for (int j = 0; j < d; j += 32) {
            int chunk = min(32, d - j);
            int idx = (lane < chunk) ? g_adj[rs + j + lane] : 0;
            int q = 0;
            for (; q + 7 < chunk; q += 8) {
                int m0 = __shfl_sync(0xffffffffu, idx, q);
                int m1 = __shfl_sync(0xffffffffu, idx, q + 1);
                int m2 = __shfl_sync(0xffffffffu, idx, q + 2);
                int m3 = __shfl_sync(0xffffffffu, idx, q + 3);
                int m4 = __shfl_sync(0xffffffffu, idx, q + 4);
                int m5 = __shfl_sync(0xffffffffu, idx, q + 5);
                int m6 = __shfl_sync(0xffffffffu, idx, q + 6);
                int m7 = __shfl_sync(0xffffffffu, idx, q + 7);
                float2 f0 = __half22float2(g_h1h[m0 * 32 + lane]);
                float2 f1 = __half22float2(g_h1h[m1 * 32 + lane]);
                float2 f2 = __half22float2(g_h1h[m2 * 32 + lane]);
                float2 f3 = __half22float2(g_h1h[m3 * 32 + lane]);
                float2 f4 = __half22float2(g_h1h[m4 * 32 + lane]);
                float2 f5 = __half22float2(g_h1h[m5 * 32 + lane]);
                float2 f6 = __half22float2(g_h1h[m6 * 32 + lane]);
                float2 f7 = __half22float2(g_h1h[m7 * 32 + lane]);
                a0 += f0.x; b0 += f0.y;
                a1 += f1.x; b1 += f1.y;
                a2 += f2.x; b2 += f2.y;
                a3 += f3.x; b3 += f3.y;
                a0 += f4.x; b0 += f4.y;
                a1 += f5.x; b1 += f5.y;
                a2 += f6.x; b2 += f6.y;
                a3 += f7.x; b3 += f7.y;
            }
            for (; q + 3 < chunk; q += 4) {
                int m0 = __shfl_sync(0xffffffffu, idx, q);
                int m1 = __shfl_sync(0xffffffffu, idx, q + 1);
                int m2 = __shfl_sync(0xffffffffu, idx, q + 2);
                int m3 = __shfl_sync(0xffffffffu, idx, q + 3);
                float2 f0 = __half22float2(g_h1h[m0 * 32 + lane]);
                float2 f1 = __half22float2(g_h1h[m1 * 32 + lane]);
                float2 f2 = __half22float2(g_h1h[m2 * 32 + lane]);
                float2 f3 = __half22float2(g_h1h[m3 * 32 + lane]);
                a0 += f0.x; b0 += f0.y;
                a1 += f1.x; b1 += f1.y;
                a2 += f2.x; b2 += f2.y;
                a3 += f3.x; b3 += f3.y;
            }
            for (; q < chunk; q++) {
                int m0 = __shfl_sync(0xffffffffu, idx, q);
                float2 f0 = __half22float2(g_h1h[m0 * 32 + lane]);
                a0 += f0.x; b0 += f0.y;
            }
        }
        float inv = d > 0 ? 1.0f / (float)d : 0.0f;
        sa2[r * 68 + lane] =
            __floats2half2_rn((a0 + a1 + a2 + a3) * inv, (b0 + b1 + b2 + b3) * inv);
        sa2[r * 68 + 32 + lane] = g_h1h[n * 32 + lane];
    }
    __syncwarp();

    // GEMM: [16 x 128] @ [128 x 64], fp32 accum
    uint32_t aBase = smem_u32(sA + warp * 16 * 136) + (uint32_t)((lane & 15) * 272 + (lane >> 4) * 16);
    uint32_t bBase = smem_u32(sB) + (uint32_t)((lane & 15) * 144);
    float c[8][4];
#pragma unroll
    for (int nt = 0; nt < 8; nt++) { c[nt][0] = c[nt][1] = c[nt][2] = c[nt][3] = 0.f; }
#pragma unroll
    for (int kk = 0; kk < 8; kk++) {
        uint32_t a0, a1, a2, a3;
        ldsm_x4(a0, a1, a2, a3, aBase + kk * 32);
#pragma unroll
        for (int nt = 0; nt < 8; nt++) {
            uint32_t b0, b1;
            ldsm_x2t(b0, b1, bBase + (uint32_t)(kk * 16 * 144 + nt * 16));
            mma16816(c[nt], a0, a1, a2, a3, b0, b1);
        }
    }
    int q = lane & 3, rlo = lane >> 2;
    float ssl = 0.f, ssh = 0.f;
#pragma unroll
    for (int nt = 0; nt < 8; nt++) {
        float bb0 = sbias[nt * 8 + q * 2], bb1 = sbias[nt * 8 + q * 2 + 1];
        c[nt][0] += bb0; c[nt][1] += bb1; c[nt][2] += bb0; c[nt][3] += bb1;
        ssl += c[nt][0] * c[nt][0] + c[nt][1] * c[nt][1];
        ssh += c[nt][2] * c[nt][2] + c[nt][3] * c[nt][3];
    }
    ssl += __shfl_xor_sync(0xffffffffu, ssl, 1);
    ssl += __shfl_xor_sync(0xffffffffu, ssl, 2);
    ssh += __shfl_xor_sync(0xffffffffu, ssh, 1);
    ssh += __shfl_xor_sync(0xffffffffu, ssh, 2);
    float il = 1.0f / fmaxf(sqrtf(ssl), 1e-12f);
    float ih = 1.0f / fmaxf(sqrtf(ssh), 1e-12f);
    int nlo = base + rlo, nhi = nlo + 8;
#pragma unroll
    for (int nt = 0; nt < 8; nt++) {
        g_h2h[nlo * 32 + nt * 4 + q] =
            __floats2half2_rn(fmaxf(c[nt][0] * il, 0.f), fmaxf(c[nt][1] * il, 0.f));
        g_h2h[nhi * 32 + nt * 4 + q] =
            __floats2half2_rn(fmaxf(c[nt][2] * ih, 0.f), fmaxf(c[nt][3] * ih, 0.f));
    }
}

// ---------------- head: pool + MLP; ALSO re-zeroes g_cnt for next call ---
__global__ void k_head(const float* __restrict__ p1w, const float* __restrict__ p1b,
                       const float* __restrict__ p2w, const float* __restrict__ p2b,
                       const float* __restrict__ ow,  const float* __restrict__ ob,
                       float* __restrict__ out) {
    __shared__ float part[4 * 64];
    __shared__ float sg[64], t1[64], t2[16];
    int g = blockIdx.x, t = threadIdx.x;
    // re-zero g_cnt (convs already consumed it this call; next call's
    // k_prehist needs it zeroed). 512 blocks x 256 threads covers N_NODES.
    int zi = g * 256 + t;
    if (zi < N_NODES) g_cnt[zi] = 0;

    int lo = g_lo[g], hi = g_lo[g + 1];
    int f = t & 63, r = t >> 6;
    float s = 0.f;
    for (int n = lo + r; n < hi; n += 4) {
        __half2 v = g_h2h[n * 32 + (f >> 1)];
        s += (f & 1) ? __half2float(__high2half(v)) : __half2float(__low2half(v));
    }
    part[r * 64 + f] = s;
    __syncthreads();
    if (t < 64) {
        float tot = part[t] + part[64 + t] + part[128 + t] + part[192 + t];
        float cnt = (float)(hi - lo);
        sg[t] = tot / fmaxf(cnt, 1.0f);
    }
    __syncthreads();
    if (t < 64) {
        float s1 = p1b[t];
#pragma unroll 8
        for (int k = 0; k < 64; k++) s1 += sg[k] * p1w[k * 64 + t];
        t1[t] = fmaxf(s1, 0.f);
    }
    __syncthreads();
    if (t < 16) {
        float s2 = p2b[t];
#pragma unroll 8
        for (int k = 0; k < 64; k++) s2 += t1[k] * p2w[k * 16 + t];
        t2[t] = fmaxf(s2, 0.f);
    }
    __syncthreads();
    if (t == 0) {
        float o = ob[0];
#pragma unroll
        for (int k = 0; k < 16; k++) o += t2[k] * ow[k];
        out[g] = o;
    }
}

// ---------------- launch ----------------
extern "C" void kernel_launch(void* const* d_in, const int* in_sizes, int n_in,
                              void* d_out, int out_size) {
    const float* x     = (const float*)d_in[0];
    const int*   ei    = (const int*)d_in[1];
    const int*   batch = (const int*)d_in[2];
    int base = (n_in >= 18 && in_sizes[3] == 1) ? 4 : 3;
    const float* pre_w = (const float*)d_in[base + 0];
    const float* pre_b = (const float*)d_in[base + 1];
    const float* c1_wl = (const float*)d_in[base + 2];
    const float* c1_bl = (const float*)d_in[base + 3];
    const float* c1_wr = (const float*)d_in[base + 4];
    const float* c2_wl = (const float*)d_in[base + 5];
    const float* c2_bl = (const float*)d_in[base + 6];
    const float* c2_wr = (const float*)d_in[base + 7];
    const float* p1_w  = (const float*)d_in[base + 8];
    const float* p1_b  = (const float*)d_in[base + 9];
    const float* p2_w  = (const float*)d_in[base + 10];
    const float* p2_b  = (const float*)d_in[base + 11];
    const float* o_w   = (const float*)d_in[base + 12];
    const float* o_b   = (const float*)d_in[base + 13];

    const int* src = ei;
    const int* dst = ei + N_EDGES;
    float* out = (float*)d_out;

    const size_t smem1 = 64 * 72 * 2 + 8 * 16 * 72 * 2 + 256;     // 27904
    const size_t smem2 = 128 * 72 * 2 + 8 * 16 * 136 * 2 + 256;   // 53504
    cudaFuncSetAttribute(k_conv1, cudaFuncAttributeMaxDynamicSharedMemorySize, (int)smem1);
    cudaFuncSetAttribute(k_conv2, cudaFuncAttributeMaxDynamicSharedMemorySize, (int)smem2);

    const int T = 256;
    k_prehist<<<PRE_BLKS + HIST_BLKS, T>>>(x, pre_w, pre_b, dst);
    k_scan1<<<NB_SCAN, 256>>>();
    k_scan23<<<PRE_BLKS, 256>>>(batch);
    k_fill<<<(N_EDGES / 4 + T - 1) / T, T>>>(src, dst);

    int nblk = (N_TILES + 7) / 8;   // 782
    k_conv1<<<nblk, 256, smem1>>>(c1_wl, c1_bl, c1_wr);
    k_conv2<<<nblk, 256, smem2>>>(c2_wl, c2_bl, c2_wr);

    k_head<<<N_GRAPHS, 256>>>(p1_w, p1_b, p2_w, p2_b, o_w, o_b, out);
    (void)out_size;
}